// round 1
// baseline (speedup 1.0000x reference)
#include <cuda_runtime.h>
#include <cuda_bf16.h>
#include <math.h>

// Problem constants (from reference)
#define T_TOK 256
#define H_DIM 1024
#define I_DIM 512
#define E_EXP 32
#define TOPK  8
#define NGRP  8
#define GSZ   4      // E / NGRP
#define TKG   4      // topk_group

// ---------------- device scratch (no allocations allowed) ----------------
__device__ int   g_topk_idx[T_TOK * TOPK];
__device__ float g_topk_w[T_TOK * TOPK];

__device__ int   g_cnt[E_EXP];
__device__ int   g_tok[E_EXP * T_TOK];
__device__ int   g_slot[E_EXP * T_TOK];
__device__ float g_wt[E_EXP * T_TOK];

__device__ float g_abuf[T_TOK * TOPK * I_DIM];   // 4 MB, rows indexed by (t*8+slot)
__device__ float g_ybuf[T_TOK * TOPK * H_DIM];   // 8 MB, rows indexed by (t*8+slot)

// ---------------- kernel 1: routing ----------------
// one block per token, 128 threads
__global__ __launch_bounds__(128) void routing_kernel(
    const float* __restrict__ x,
    const float* __restrict__ gate_w,
    const float* __restrict__ bias)
{
    int t = blockIdx.x;
    __shared__ float xs[H_DIM];
    __shared__ float sc[E_EXP];    // raw sigmoid scores
    __shared__ float sfc[E_EXP];   // scores + bias

    int tid = threadIdx.x;
    for (int i = tid; i < H_DIM; i += 128) xs[i] = x[(size_t)t * H_DIM + i];
    __syncthreads();

    int warp = tid >> 5, lane = tid & 31;
    for (int e = warp; e < E_EXP; e += 4) {
        float s = 0.f;
        for (int h = lane; h < H_DIM; h += 32)
            s += xs[h] * gate_w[(size_t)h * E_EXP + e];
        #pragma unroll
        for (int o = 16; o; o >>= 1) s += __shfl_xor_sync(0xffffffffu, s, o);
        if (lane == 0) {
            float sig = 1.f / (1.f + expf(-s));
            sc[e]  = sig;
            sfc[e] = sig + bias[e];
        }
    }
    __syncthreads();

    if (tid == 0) {
        // group scores = sum of top-2 within each group of 4
        float gs[NGRP];
        #pragma unroll
        for (int g = 0; g < NGRP; g++) {
            float m1 = -1e30f, m2 = -1e30f;
            #pragma unroll
            for (int j = 0; j < GSZ; j++) {
                float v = sfc[g * GSZ + j];
                if (v > m1) { m2 = m1; m1 = v; }
                else if (v > m2) { m2 = v; }
            }
            gs[g] = m1 + m2;
        }
        // top-4 groups (value desc, index asc on ties)
        bool gsel[NGRP];
        #pragma unroll
        for (int g = 0; g < NGRP; g++) gsel[g] = false;
        for (int r = 0; r < TKG; r++) {
            int b = -1;
            for (int g = 0; g < NGRP; g++)
                if (!gsel[g] && (b < 0 || gs[g] > gs[b])) b = g;
            gsel[b] = true;
        }
        // masked scores: kept groups use sfc, else exactly 0.0 (matches jnp.where)
        float masked[E_EXP];
        bool used[E_EXP];
        #pragma unroll
        for (int e = 0; e < E_EXP; e++) {
            masked[e] = gsel[e >> 2] ? sfc[e] : 0.0f;
            used[e] = false;
        }
        // top-8 of masked (value desc, index asc); weights gather RAW scores sc[]
        int idx[TOPK];
        float wsum = 0.f;
        for (int r = 0; r < TOPK; r++) {
            int b = -1;
            for (int e = 0; e < E_EXP; e++)
                if (!used[e] && (b < 0 || masked[e] > masked[b])) b = e;
            used[b] = true;
            idx[r] = b;
            wsum += sc[b];
        }
        float scale = 2.5f / (wsum + 1e-20f);
        for (int r = 0; r < TOPK; r++) {
            g_topk_idx[t * TOPK + r] = idx[r];
            g_topk_w[t * TOPK + r]   = sc[idx[r]] * scale;
        }
    }
}

// ---------------- kernel 2: deterministic per-expert compaction ----------------
__global__ void build_lists_kernel()
{
    int e = threadIdx.x;   // 32 threads, one per expert
    int cnt = 0;
    for (int t = 0; t < T_TOK; t++) {
        #pragma unroll
        for (int k = 0; k < TOPK; k++) {
            if (g_topk_idx[t * TOPK + k] == e) {
                g_tok [e * T_TOK + cnt] = t;
                g_slot[e * T_TOK + cnt] = k;
                g_wt  [e * T_TOK + cnt] = g_topk_w[t * TOPK + k];
                cnt++;
            }
        }
    }
    g_cnt[e] = cnt;
}

// ---------------- kernel 3: gate + up + silu fused ----------------
// C tiles 64x64, K tile 16, 256 threads, 4x4 register blocking, dual B (Wg, Wu)
#define BM 64
#define BN 64
#define BK 16
__global__ __launch_bounds__(256) void gateup_kernel(
    const float* __restrict__ x,
    const float* __restrict__ Wg,
    const float* __restrict__ Wu)
{
    int nt = blockIdx.x;            // I / 64 = 8
    int mt = blockIdx.y;            // up to 4 token tiles
    int e  = blockIdx.z;            // 32 experts
    int ne = g_cnt[e];
    int m0 = mt * BM;
    if (m0 >= ne) return;

    __shared__ float Xs[BK][BM + 2];
    __shared__ __align__(16) float Gs[BK][BN];
    __shared__ __align__(16) float Us[BK][BN];
    __shared__ int toks[BM];

    int tid = threadIdx.x;
    if (tid < BM) toks[tid] = (m0 + tid < ne) ? g_tok[e * T_TOK + m0 + tid] : -1;
    __syncthreads();

    int tx = tid & 15, ty = tid >> 4;
    float ag[4][4], au[4][4];
    #pragma unroll
    for (int i = 0; i < 4; i++)
        #pragma unroll
        for (int j = 0; j < 4; j++) { ag[i][j] = 0.f; au[i][j] = 0.f; }

    const float* wgB = Wg + (size_t)e * H_DIM * I_DIM + nt * BN;
    const float* wuB = Wu + (size_t)e * H_DIM * I_DIM + nt * BN;

    for (int kt = 0; kt < H_DIM; kt += BK) {
        #pragma unroll
        for (int j = 0; j < 4; j++) {
            int el = tid + j * 256;
            int r = el >> 4, kk = el & 15;
            int tok = toks[r];
            Xs[kk][r] = (tok >= 0) ? x[(size_t)tok * H_DIM + kt + kk] : 0.f;
        }
        #pragma unroll
        for (int j = 0; j < 4; j++) {
            int el = tid + j * 256;
            int kk = el >> 6, c = el & 63;
            Gs[kk][c] = wgB[(size_t)(kt + kk) * I_DIM + c];
            Us[kk][c] = wuB[(size_t)(kt + kk) * I_DIM + c];
        }
        __syncthreads();
        #pragma unroll
        for (int kk = 0; kk < BK; kk++) {
            float a0 = Xs[kk][ty * 4 + 0];
            float a1 = Xs[kk][ty * 4 + 1];
            float a2 = Xs[kk][ty * 4 + 2];
            float a3 = Xs[kk][ty * 4 + 3];
            float4 bg = *(const float4*)&Gs[kk][tx * 4];
            float4 bu = *(const float4*)&Us[kk][tx * 4];
            ag[0][0] += a0 * bg.x; ag[0][1] += a0 * bg.y; ag[0][2] += a0 * bg.z; ag[0][3] += a0 * bg.w;
            ag[1][0] += a1 * bg.x; ag[1][1] += a1 * bg.y; ag[1][2] += a1 * bg.z; ag[1][3] += a1 * bg.w;
            ag[2][0] += a2 * bg.x; ag[2][1] += a2 * bg.y; ag[2][2] += a2 * bg.z; ag[2][3] += a2 * bg.w;
            ag[3][0] += a3 * bg.x; ag[3][1] += a3 * bg.y; ag[3][2] += a3 * bg.z; ag[3][3] += a3 * bg.w;
            au[0][0] += a0 * bu.x; au[0][1] += a0 * bu.y; au[0][2] += a0 * bu.z; au[0][3] += a0 * bu.w;
            au[1][0] += a1 * bu.x; au[1][1] += a1 * bu.y; au[1][2] += a1 * bu.z; au[1][3] += a1 * bu.w;
            au[2][0] += a2 * bu.x; au[2][1] += a2 * bu.y; au[2][2] += a2 * bu.z; au[2][3] += a2 * bu.w;
            au[3][0] += a3 * bu.x; au[3][1] += a3 * bu.y; au[3][2] += a3 * bu.z; au[3][3] += a3 * bu.w;
        }
        __syncthreads();
    }

    // epilogue: a = silu(g) * u  ->  abuf[(tok*8+slot)*I + i]
    #pragma unroll
    for (int i = 0; i < 4; i++) {
        int m = ty * 4 + i;
        if (m0 + m >= ne) continue;
        int tok  = toks[m];
        int slot = g_slot[e * T_TOK + m0 + m];
        size_t rowo = ((size_t)tok * TOPK + slot) * I_DIM + nt * BN + tx * 4;
        #pragma unroll
        for (int j = 0; j < 4; j++) {
            float g = ag[i][j];
            float u = au[i][j];
            float a = (g / (1.f + expf(-g))) * u;
            g_abuf[rowo + j] = a;
        }
    }
}

// ---------------- kernel 4: down projection (scaled by routing weight) ----------------
__global__ __launch_bounds__(256) void down_kernel(
    const float* __restrict__ Wd)
{
    int nt = blockIdx.x;            // H / 64 = 16
    int mt = blockIdx.y;            // up to 4
    int e  = blockIdx.z;            // 32
    int ne = g_cnt[e];
    int m0 = mt * BM;
    if (m0 >= ne) return;

    __shared__ float As[BK][BM + 2];
    __shared__ __align__(16) float Ds[BK][BN];
    __shared__ int   rows[BM];
    __shared__ float wts[BM];

    int tid = threadIdx.x;
    if (tid < BM) {
        if (m0 + tid < ne) {
            int tok  = g_tok [e * T_TOK + m0 + tid];
            int slot = g_slot[e * T_TOK + m0 + tid];
            rows[tid] = tok * TOPK + slot;
            wts[tid]  = g_wt[e * T_TOK + m0 + tid];
        } else {
            rows[tid] = -1;
            wts[tid]  = 0.f;
        }
    }
    __syncthreads();

    int tx = tid & 15, ty = tid >> 4;
    float acc[4][4];
    #pragma unroll
    for (int i = 0; i < 4; i++)
        #pragma unroll
        for (int j = 0; j < 4; j++) acc[i][j] = 0.f;

    const float* wdB = Wd + (size_t)e * I_DIM * H_DIM + nt * BN;

    for (int kt = 0; kt < I_DIM; kt += BK) {
        #pragma unroll
        for (int j = 0; j < 4; j++) {
            int el = tid + j * 256;
            int r = el >> 4, kk = el & 15;
            int row = rows[r];
            As[kk][r] = (row >= 0) ? g_abuf[(size_t)row * I_DIM + kt + kk] : 0.f;
        }
        #pragma unroll
        for (int j = 0; j < 4; j++) {
            int el = tid + j * 256;
            int kk = el >> 6, c = el & 63;
            Ds[kk][c] = wdB[(size_t)(kt + kk) * H_DIM + c];
        }
        __syncthreads();
        #pragma unroll
        for (int kk = 0; kk < BK; kk++) {
            float a0 = As[kk][ty * 4 + 0];
            float a1 = As[kk][ty * 4 + 1];
            float a2 = As[kk][ty * 4 + 2];
            float a3 = As[kk][ty * 4 + 3];
            float4 b = *(const float4*)&Ds[kk][tx * 4];
            acc[0][0] += a0 * b.x; acc[0][1] += a0 * b.y; acc[0][2] += a0 * b.z; acc[0][3] += a0 * b.w;
            acc[1][0] += a1 * b.x; acc[1][1] += a1 * b.y; acc[1][2] += a1 * b.z; acc[1][3] += a1 * b.w;
            acc[2][0] += a2 * b.x; acc[2][1] += a2 * b.y; acc[2][2] += a2 * b.z; acc[2][3] += a2 * b.w;
            acc[3][0] += a3 * b.x; acc[3][1] += a3 * b.y; acc[3][2] += a3 * b.z; acc[3][3] += a3 * b.w;
        }
        __syncthreads();
    }

    #pragma unroll
    for (int i = 0; i < 4; i++) {
        int m = ty * 4 + i;
        if (m0 + m >= ne) continue;
        int row = rows[m];
        float w = wts[m];
        size_t rowo = (size_t)row * H_DIM + nt * BN + tx * 4;
        #pragma unroll
        for (int j = 0; j < 4; j++)
            g_ybuf[rowo + j] = w * acc[i][j];
    }
}

// ---------------- kernel 5: deterministic combine ----------------
__global__ __launch_bounds__(256) void combine_kernel(float* __restrict__ out)
{
    int idx = blockIdx.x * 256 + threadIdx.x;   // T*H threads
    int t = idx >> 10;
    int h = idx & 1023;
    float s = 0.f;
    #pragma unroll
    for (int k = 0; k < TOPK; k++)
        s += g_ybuf[((size_t)t * TOPK + k) * H_DIM + h];
    out[idx] = s;
}

// ---------------- launch ----------------
extern "C" void kernel_launch(void* const* d_in, const int* in_sizes, int n_in,
                              void* d_out, int out_size)
{
    const float* x      = (const float*)d_in[0];
    const float* gate_w = (const float*)d_in[1];
    const float* bias   = (const float*)d_in[2];
    const float* Wg     = (const float*)d_in[3];
    const float* Wu     = (const float*)d_in[4];
    const float* Wd     = (const float*)d_in[5];
    float* out = (float*)d_out;

    routing_kernel<<<T_TOK, 128>>>(x, gate_w, bias);
    build_lists_kernel<<<1, E_EXP>>>();
    gateup_kernel<<<dim3(I_DIM / BN, T_TOK / BM, E_EXP), 256>>>(x, Wg, Wu);
    down_kernel<<<dim3(H_DIM / BN, T_TOK / BM, E_EXP), 256>>>(Wd);
    combine_kernel<<<(T_TOK * H_DIM) / 256, 256>>>(out);
}

// round 2
// speedup vs baseline: 1.1549x; 1.1549x over previous
#include <cuda_runtime.h>
#include <cuda_bf16.h>
#include <math.h>

// Problem constants (from reference)
#define T_TOK 256
#define H_DIM 1024
#define I_DIM 512
#define E_EXP 32
#define TOPK  8
#define NGRP  8
#define GSZ   4      // E / NGROUP
#define TKG   4      // topk_group

typedef unsigned long long ull;

// packed fp32x2 FMA (Blackwell): d = a*b + d, element-wise on 2 floats
__device__ __forceinline__ void fma2(ull &d, ull a, ull b) {
    asm("fma.rn.f32x2 %0, %1, %2, %0;" : "+l"(d) : "l"(a), "l"(b));
}
__device__ __forceinline__ float2 unpack2(ull v) {
    float2 r;
    asm("mov.b64 {%0, %1}, %2;" : "=f"(r.x), "=f"(r.y) : "l"(v));
    return r;
}

// ---------------- device scratch ----------------
__device__ int   g_topk_idx[T_TOK * TOPK];
__device__ float g_topk_w[T_TOK * TOPK];

__device__ int   g_cnt[E_EXP];
__device__ int   g_tok[E_EXP * T_TOK];
__device__ int   g_slot[E_EXP * T_TOK];
__device__ float g_wt[E_EXP * T_TOK];

__device__ float g_abuf[T_TOK * TOPK * I_DIM];   // rows indexed by (t*8+slot)
__device__ float g_ybuf[T_TOK * TOPK * H_DIM];

// ---------------- kernel 1: routing ----------------
__global__ __launch_bounds__(128) void routing_kernel(
    const float* __restrict__ x,
    const float* __restrict__ gate_w,
    const float* __restrict__ bias)
{
    int t = blockIdx.x;
    __shared__ float xs[H_DIM];
    __shared__ float sc[E_EXP];
    __shared__ float sfc[E_EXP];

    int tid = threadIdx.x;
    for (int i = tid; i < H_DIM; i += 128) xs[i] = x[(size_t)t * H_DIM + i];
    __syncthreads();

    int warp = tid >> 5, lane = tid & 31;
    for (int e = warp; e < E_EXP; e += 4) {
        float s = 0.f;
        for (int h = lane; h < H_DIM; h += 32)
            s += xs[h] * gate_w[(size_t)h * E_EXP + e];
        #pragma unroll
        for (int o = 16; o; o >>= 1) s += __shfl_xor_sync(0xffffffffu, s, o);
        if (lane == 0) {
            float sig = 1.f / (1.f + expf(-s));
            sc[e]  = sig;
            sfc[e] = sig + bias[e];
        }
    }
    __syncthreads();

    if (tid == 0) {
        float gs[NGRP];
        #pragma unroll
        for (int g = 0; g < NGRP; g++) {
            float m1 = -1e30f, m2 = -1e30f;
            #pragma unroll
            for (int j = 0; j < GSZ; j++) {
                float v = sfc[g * GSZ + j];
                if (v > m1) { m2 = m1; m1 = v; }
                else if (v > m2) { m2 = v; }
            }
            gs[g] = m1 + m2;
        }
        bool gsel[NGRP];
        #pragma unroll
        for (int g = 0; g < NGRP; g++) gsel[g] = false;
        for (int r = 0; r < TKG; r++) {
            int b = -1;
            for (int g = 0; g < NGRP; g++)
                if (!gsel[g] && (b < 0 || gs[g] > gs[b])) b = g;
            gsel[b] = true;
        }
        float masked[E_EXP];
        bool used[E_EXP];
        #pragma unroll
        for (int e = 0; e < E_EXP; e++) {
            masked[e] = gsel[e >> 2] ? sfc[e] : 0.0f;
            used[e] = false;
        }
        int idx[TOPK];
        float wsum = 0.f;
        for (int r = 0; r < TOPK; r++) {
            int b = -1;
            for (int e = 0; e < E_EXP; e++)
                if (!used[e] && (b < 0 || masked[e] > masked[b])) b = e;
            used[b] = true;
            idx[r] = b;
            wsum += sc[b];
        }
        float scale = 2.5f / (wsum + 1e-20f);
        for (int r = 0; r < TOPK; r++) {
            g_topk_idx[t * TOPK + r] = idx[r];
            g_topk_w[t * TOPK + r]   = sc[idx[r]] * scale;
        }
    }
}

// ---------------- kernel 2: deterministic compaction ----------------
__global__ void build_lists_kernel()
{
    int e = threadIdx.x;
    int cnt = 0;
    for (int t = 0; t < T_TOK; t++) {
        #pragma unroll
        for (int k = 0; k < TOPK; k++) {
            if (g_topk_idx[t * TOPK + k] == e) {
                g_tok [e * T_TOK + cnt] = t;
                g_slot[e * T_TOK + cnt] = k;
                g_wt  [e * T_TOK + cnt] = g_topk_w[t * TOPK + k];
                cnt++;
            }
        }
    }
    g_cnt[e] = cnt;
}

// ---------------- kernel 3: gate + up + silu (f32x2 GEMM) ----------------
// 64x64 tile, BK=16, 256 threads, per-thread 4 rows x 4 cols x 2 matrices
#define BM 64
#define BN 64
#define BK 16
#define XROW 36   // duplicated X row stride in floats (32 data + 4 pad), 144B = 9*16

__global__ __launch_bounds__(256) void gateup_kernel(
    const float* __restrict__ x,
    const float* __restrict__ Wg,
    const float* __restrict__ Wu)
{
    int nt = blockIdx.x;            // I/64 = 8
    int mt = blockIdx.y;            // 4
    int e  = blockIdx.z;            // 32
    int ne = g_cnt[e];
    int m0 = mt * BM;
    if (m0 >= ne) return;

    __shared__ __align__(16) float XsD[BM][XROW];   // duplicated: XsD[m][2k]=XsD[m][2k+1]=x
    __shared__ __align__(16) float Gs[BK][BN];
    __shared__ __align__(16) float Us[BK][BN];
    __shared__ int toks[BM];

    int tid = threadIdx.x;
    if (tid < BM) toks[tid] = (m0 + tid < ne) ? g_tok[e * T_TOK + m0 + tid] : -1;
    __syncthreads();

    // load-stage indices
    int xm = tid >> 2;               // 0..63
    int xk = (tid & 3) * 4;          // 0,4,8,12
    int gk = tid >> 4;               // 0..15
    int gc = (tid & 15) * 4;         // 0..60

    const float* wgB = Wg + (size_t)e * H_DIM * I_DIM + nt * BN;
    const float* wuB = Wu + (size_t)e * H_DIM * I_DIM + nt * BN;
    int tok0 = toks[xm];
    const float* xrow = (tok0 >= 0) ? (x + (size_t)tok0 * H_DIM) : x;

    float4 xr = make_float4(0.f, 0.f, 0.f, 0.f);
    if (tok0 >= 0) xr = *(const float4*)(xrow + xk);
    float4 gr = *(const float4*)(wgB + (size_t)gk * I_DIM + gc);
    float4 ur = *(const float4*)(wuB + (size_t)gk * I_DIM + gc);

    int tx = tid & 15, ty = tid >> 4;
    ull accg[4][2], accu[4][2];
    #pragma unroll
    for (int i = 0; i < 4; i++) {
        accg[i][0] = 0ull; accg[i][1] = 0ull;
        accu[i][0] = 0ull; accu[i][1] = 0ull;
    }

    for (int kt = 0; kt < H_DIM; kt += BK) {
        // store current tile (X duplicated)
        {
            float4 d0 = make_float4(xr.x, xr.x, xr.y, xr.y);
            float4 d1 = make_float4(xr.z, xr.z, xr.w, xr.w);
            *(float4*)&XsD[xm][2 * xk]     = d0;
            *(float4*)&XsD[xm][2 * xk + 4] = d1;
            *(float4*)&Gs[gk][gc] = gr;
            *(float4*)&Us[gk][gc] = ur;
        }
        __syncthreads();

        int ktn = kt + BK;
        if (ktn < H_DIM) {
            if (tok0 >= 0) xr = *(const float4*)(xrow + ktn + xk);
            gr = *(const float4*)(wgB + (size_t)(ktn + gk) * I_DIM + gc);
            ur = *(const float4*)(wuB + (size_t)(ktn + gk) * I_DIM + gc);
        }

        #pragma unroll
        for (int kc = 0; kc < BK; kc += 4) {
            ull ap[4][4];
            #pragma unroll
            for (int i = 0; i < 4; i++) {
                longlong2 a01 = *(const longlong2*)&XsD[ty * 4 + i][2 * kc];
                longlong2 a23 = *(const longlong2*)&XsD[ty * 4 + i][2 * kc + 4];
                ap[i][0] = (ull)a01.x; ap[i][1] = (ull)a01.y;
                ap[i][2] = (ull)a23.x; ap[i][3] = (ull)a23.y;
            }
            #pragma unroll
            for (int q = 0; q < 4; q++) {
                longlong2 bg = *(const longlong2*)&Gs[kc + q][tx * 4];
                longlong2 bu = *(const longlong2*)&Us[kc + q][tx * 4];
                #pragma unroll
                for (int i = 0; i < 4; i++) {
                    fma2(accg[i][0], ap[i][q], (ull)bg.x);
                    fma2(accg[i][1], ap[i][q], (ull)bg.y);
                    fma2(accu[i][0], ap[i][q], (ull)bu.x);
                    fma2(accu[i][1], ap[i][q], (ull)bu.y);
                }
            }
        }
        __syncthreads();
    }

    // epilogue: a = silu(g)*u
    #pragma unroll
    for (int i = 0; i < 4; i++) {
        int m = ty * 4 + i;
        if (m0 + m >= ne) continue;
        int tok  = toks[m];
        int slot = g_slot[e * T_TOK + m0 + m];
        size_t rowo = ((size_t)tok * TOPK + slot) * I_DIM + nt * BN + tx * 4;
        float gv[4], uv[4];
        float2 t0 = unpack2(accg[i][0]); gv[0] = t0.x; gv[1] = t0.y;
        float2 t1 = unpack2(accg[i][1]); gv[2] = t1.x; gv[3] = t1.y;
        float2 t2 = unpack2(accu[i][0]); uv[0] = t2.x; uv[1] = t2.y;
        float2 t3 = unpack2(accu[i][1]); uv[2] = t3.x; uv[3] = t3.y;
        #pragma unroll
        for (int j = 0; j < 4; j++) {
            float g = gv[j];
            g_abuf[rowo + j] = (g / (1.f + expf(-g))) * uv[j];
        }
    }
}

// ---------------- kernel 4: down projection (f32x2 GEMM) ----------------
__global__ __launch_bounds__(256) void down_kernel(
    const float* __restrict__ Wd)
{
    int nt = blockIdx.x;            // H/64 = 16
    int mt = blockIdx.y;            // 4
    int e  = blockIdx.z;            // 32
    int ne = g_cnt[e];
    int m0 = mt * BM;
    if (m0 >= ne) return;

    __shared__ __align__(16) float AsD[BM][XROW];
    __shared__ __align__(16) float Ds[BK][BN];
    __shared__ int   rows[BM];
    __shared__ float wts[BM];

    int tid = threadIdx.x;
    if (tid < BM) {
        if (m0 + tid < ne) {
            int tok  = g_tok [e * T_TOK + m0 + tid];
            int slot = g_slot[e * T_TOK + m0 + tid];
            rows[tid] = tok * TOPK + slot;
            wts[tid]  = g_wt[e * T_TOK + m0 + tid];
        } else {
            rows[tid] = -1;
            wts[tid]  = 0.f;
        }
    }
    __syncthreads();

    int xm = tid >> 2;
    int xk = (tid & 3) * 4;
    int gk = tid >> 4;
    int gc = (tid & 15) * 4;

    const float* wdB = Wd + (size_t)e * I_DIM * H_DIM + nt * BN;
    int row0 = rows[xm];
    const float* arow = (row0 >= 0) ? (g_abuf + (size_t)row0 * I_DIM) : g_abuf;

    float4 ar = make_float4(0.f, 0.f, 0.f, 0.f);
    if (row0 >= 0) ar = *(const float4*)(arow + xk);
    float4 dr = *(const float4*)(wdB + (size_t)gk * H_DIM + gc);

    int tx = tid & 15, ty = tid >> 4;
    ull acc[4][2];
    #pragma unroll
    for (int i = 0; i < 4; i++) { acc[i][0] = 0ull; acc[i][1] = 0ull; }

    for (int kt = 0; kt < I_DIM; kt += BK) {
        {
            float4 d0 = make_float4(ar.x, ar.x, ar.y, ar.y);
            float4 d1 = make_float4(ar.z, ar.z, ar.w, ar.w);
            *(float4*)&AsD[xm][2 * xk]     = d0;
            *(float4*)&AsD[xm][2 * xk + 4] = d1;
            *(float4*)&Ds[gk][gc] = dr;
        }
        __syncthreads();

        int ktn = kt + BK;
        if (ktn < I_DIM) {
            if (row0 >= 0) ar = *(const float4*)(arow + ktn + xk);
            dr = *(const float4*)(wdB + (size_t)(ktn + gk) * H_DIM + gc);
        }

        #pragma unroll
        for (int kc = 0; kc < BK; kc += 4) {
            ull ap[4][4];
            #pragma unroll
            for (int i = 0; i < 4; i++) {
                longlong2 a01 = *(const longlong2*)&AsD[ty * 4 + i][2 * kc];
                longlong2 a23 = *(const longlong2*)&AsD[ty * 4 + i][2 * kc + 4];
                ap[i][0] = (ull)a01.x; ap[i][1] = (ull)a01.y;
                ap[i][2] = (ull)a23.x; ap[i][3] = (ull)a23.y;
            }
            #pragma unroll
            for (int q = 0; q < 4; q++) {
                longlong2 bd = *(const longlong2*)&Ds[kc + q][tx * 4];
                #pragma unroll
                for (int i = 0; i < 4; i++) {
                    fma2(acc[i][0], ap[i][q], (ull)bd.x);
                    fma2(acc[i][1], ap[i][q], (ull)bd.y);
                }
            }
        }
        __syncthreads();
    }

    #pragma unroll
    for (int i = 0; i < 4; i++) {
        int m = ty * 4 + i;
        if (m0 + m >= ne) continue;
        int row = rows[m];
        float w = wts[m];
        size_t rowo = (size_t)row * H_DIM + nt * BN + tx * 4;
        float2 t0 = unpack2(acc[i][0]);
        float2 t1 = unpack2(acc[i][1]);
        g_ybuf[rowo + 0] = w * t0.x;
        g_ybuf[rowo + 1] = w * t0.y;
        g_ybuf[rowo + 2] = w * t1.x;
        g_ybuf[rowo + 3] = w * t1.y;
    }
}

// ---------------- kernel 5: deterministic combine ----------------
__global__ __launch_bounds__(256) void combine_kernel(float* __restrict__ out)
{
    int idx = blockIdx.x * 256 + threadIdx.x;
    int t = idx >> 10;
    int h = idx & 1023;
    float s = 0.f;
    #pragma unroll
    for (int k = 0; k < TOPK; k++)
        s += g_ybuf[((size_t)t * TOPK + k) * H_DIM + h];
    out[idx] = s;
}

// ---------------- launch ----------------
extern "C" void kernel_launch(void* const* d_in, const int* in_sizes, int n_in,
                              void* d_out, int out_size)
{
    const float* x      = (const float*)d_in[0];
    const float* gate_w = (const float*)d_in[1];
    const float* bias   = (const float*)d_in[2];
    const float* Wg     = (const float*)d_in[3];
    const float* Wu     = (const float*)d_in[4];
    const float* Wd     = (const float*)d_in[5];
    float* out = (float*)d_out;

    routing_kernel<<<T_TOK, 128>>>(x, gate_w, bias);
    build_lists_kernel<<<1, E_EXP>>>();
    gateup_kernel<<<dim3(I_DIM / BN, T_TOK / BM, E_EXP), 256>>>(x, Wg, Wu);
    down_kernel<<<dim3(H_DIM / BN, T_TOK / BM, E_EXP), 256>>>(Wd);
    combine_kernel<<<(T_TOK * H_DIM) / 256, 256>>>(out);
}

// round 4
// speedup vs baseline: 1.8727x; 1.6214x over previous
#include <cuda_runtime.h>
#include <cuda_bf16.h>
#include <math.h>
#include <stdint.h>

#define T_TOK 256
#define H_DIM 1024
#define I_DIM 512
#define E_EXP 32
#define TOPK  8
#define NGRP  8
#define GSZ   4
#define TKG   4

// SW128 swizzle on byte offsets within a 128B-row tile
#define SWZB(o) ((o) ^ (((o) >> 3) & 0x70))

// ---------------- helpers ----------------
__device__ __forceinline__ uint32_t smem_u32(const void* p) {
    uint32_t a;
    asm("{ .reg .u64 t; cvta.to.shared.u64 t, %1; cvt.u32.u64 %0, t; }" : "=r"(a) : "l"(p));
    return a;
}

// split 2 fp32 -> packed bf16x2 hi + bf16x2 lo (lo = exact residual, rn)
// low 16 bits of result = first element (lower k address)
__device__ __forceinline__ void bsplit2(float e0, float e1, uint32_t &h, uint32_t &l) {
    asm("cvt.rn.bf16x2.f32 %0, %1, %2;" : "=r"(h) : "f"(e1), "f"(e0));
    float f0 = __uint_as_float(h << 16);
    float f1 = __uint_as_float(h & 0xFFFF0000u);
    float r0 = e0 - f0, r1 = e1 - f1;
    asm("cvt.rn.bf16x2.f32 %0, %1, %2;" : "=r"(l) : "f"(r1), "f"(r0));
}

__device__ __forceinline__ void ldm4(uint32_t r[4], uint32_t addr) {
    asm volatile("ldmatrix.sync.aligned.m8n8.x4.shared.b16 {%0,%1,%2,%3}, [%4];"
        : "=r"(r[0]), "=r"(r[1]), "=r"(r[2]), "=r"(r[3]) : "r"(addr));
}

__device__ __forceinline__ void mma16816(float d[4], const uint32_t a[4],
                                         uint32_t b0, uint32_t b1) {
    asm volatile("mma.sync.aligned.m16n8k16.row.col.f32.bf16.bf16.f32 "
        "{%0,%1,%2,%3}, {%4,%5,%6,%7}, {%8,%9}, {%0,%1,%2,%3};"
        : "+f"(d[0]), "+f"(d[1]), "+f"(d[2]), "+f"(d[3])
        : "r"(a[0]), "r"(a[1]), "r"(a[2]), "r"(a[3]), "r"(b0), "r"(b1));
}

// ---------------- device scratch ----------------
__device__ int   g_topk_idx[T_TOK * TOPK];
__device__ float g_topk_w[T_TOK * TOPK];
__device__ int   g_cnt[E_EXP];
__device__ int   g_tok[E_EXP * T_TOK];
__device__ int   g_slot[E_EXP * T_TOK];
__device__ float g_wt[E_EXP * T_TOK];
__device__ float g_abuf[T_TOK * TOPK * I_DIM];
__device__ float g_ybuf[T_TOK * TOPK * H_DIM];

// ---------------- kernel 1: routing ----------------
__global__ __launch_bounds__(128) void routing_kernel(
    const float* __restrict__ x, const float* __restrict__ gate_w,
    const float* __restrict__ bias)
{
    int t = blockIdx.x;
    __shared__ float xs[H_DIM];
    __shared__ float sc[E_EXP];
    __shared__ float sfc[E_EXP];
    int tid = threadIdx.x;
    for (int i = tid; i < H_DIM; i += 128) xs[i] = x[(size_t)t * H_DIM + i];
    __syncthreads();
    int warp = tid >> 5, lane = tid & 31;
    for (int e = warp; e < E_EXP; e += 4) {
        float s = 0.f;
        for (int h = lane; h < H_DIM; h += 32)
            s += xs[h] * gate_w[(size_t)h * E_EXP + e];
        #pragma unroll
        for (int o = 16; o; o >>= 1) s += __shfl_xor_sync(0xffffffffu, s, o);
        if (lane == 0) {
            float sig = 1.f / (1.f + expf(-s));
            sc[e] = sig;
            sfc[e] = sig + bias[e];
        }
    }
    __syncthreads();
    if (tid == 0) {
        float gs[NGRP];
        #pragma unroll
        for (int g = 0; g < NGRP; g++) {
            float m1 = -1e30f, m2 = -1e30f;
            #pragma unroll
            for (int j = 0; j < GSZ; j++) {
                float v = sfc[g * GSZ + j];
                if (v > m1) { m2 = m1; m1 = v; }
                else if (v > m2) { m2 = v; }
            }
            gs[g] = m1 + m2;
        }
        bool gsel[NGRP];
        #pragma unroll
        for (int g = 0; g < NGRP; g++) gsel[g] = false;
        for (int r = 0; r < TKG; r++) {
            int b = -1;
            for (int g = 0; g < NGRP; g++)
                if (!gsel[g] && (b < 0 || gs[g] > gs[b])) b = g;
            gsel[b] = true;
        }
        float masked[E_EXP];
        bool used[E_EXP];
        #pragma unroll
        for (int e = 0; e < E_EXP; e++) {
            masked[e] = gsel[e >> 2] ? sfc[e] : 0.0f;
            used[e] = false;
        }
        int idx[TOPK];
        float wsum = 0.f;
        for (int r = 0; r < TOPK; r++) {
            int b = -1;
            for (int e = 0; e < E_EXP; e++)
                if (!used[e] && (b < 0 || masked[e] > masked[b])) b = e;
            used[b] = true;
            idx[r] = b;
            wsum += sc[b];
        }
        float scale = 2.5f / (wsum + 1e-20f);
        for (int r = 0; r < TOPK; r++) {
            g_topk_idx[t * TOPK + r] = idx[r];
            g_topk_w[t * TOPK + r]   = sc[idx[r]] * scale;
        }
    }
}

// ---------------- kernel 2: deterministic compaction ----------------
__global__ void build_lists_kernel()
{
    int e = threadIdx.x;
    int cnt = 0;
    for (int t = 0; t < T_TOK; t++) {
        #pragma unroll
        for (int k = 0; k < TOPK; k++) {
            if (g_topk_idx[t * TOPK + k] == e) {
                g_tok [e * T_TOK + cnt] = t;
                g_slot[e * T_TOK + cnt] = k;
                g_wt  [e * T_TOK + cnt] = g_topk_w[t * TOPK + k];
                cnt++;
            }
        }
    }
    g_cnt[e] = cnt;
}

// ---------------- kernel 3: gate+up HMMA bf16 hi/lo ----------------
// CTA: 64 tokens x 64 I-cols, K chunks of 64 over H.  8 warps, warp tile 32x16.
// smem tiles: A hi/lo, Bg hi/lo, Bu hi/lo : each [64 rows][64 bf16] = 8KB, SW128.
#define TILE_B 8192

__global__ __launch_bounds__(256) void gateup_kernel(
    const float* __restrict__ x,
    const float* __restrict__ Wg,
    const float* __restrict__ Wu)
{
    const int nt = blockIdx.x;   // 8  (I / 64)
    const int mt = blockIdx.y;   // 4
    const int e  = blockIdx.z;   // 32
    int ne = g_cnt[e];
    int m0 = mt * 64;
    if (m0 >= ne) return;

    extern __shared__ __align__(128) char dsm[];
    char* Ahi = dsm;
    char* Alo = dsm + TILE_B;
    char* Bgh = dsm + 2 * TILE_B;
    char* Bgl = dsm + 3 * TILE_B;
    char* Buh = dsm + 4 * TILE_B;
    char* Bul = dsm + 5 * TILE_B;
    __shared__ int s_toks[64];
    __shared__ int s_rids[64];

    int tid = threadIdx.x;
    int lane = tid & 31;
    int w = tid >> 5;
    int wm = w & 1;          // m half (0/1)
    int wn = w >> 1;         // n strip (0..3)

    if (tid < 64) {
        int i = m0 + tid;
        if (i < ne) {
            int tk = g_tok[e * T_TOK + i];
            s_toks[tid] = tk;
            s_rids[tid] = tk * TOPK + g_slot[e * T_TOK + i];
        } else { s_toks[tid] = -1; s_rids[tid] = -1; }
    }
    __syncthreads();

    uint32_t uAhi = smem_u32(Ahi), uAlo = smem_u32(Alo);
    uint32_t uBgh = smem_u32(Bgh), uBgl = smem_u32(Bgl);
    uint32_t uBuh = smem_u32(Buh), uBul = smem_u32(Bul);

    // ldmatrix lane address components
    int aRow = wm * 32 + (lane & 15);
    uint32_t aKb  = (uint32_t)((lane >> 4) * 16);            // bytes
    int bRow = wn * 16 + (lane & 7) + ((lane >> 4) << 3);
    uint32_t bKb  = (uint32_t)(((lane >> 3) & 1) * 16);

    float accg[2][2][4], accu[2][2][4];
    #pragma unroll
    for (int a = 0; a < 2; a++)
        #pragma unroll
        for (int b = 0; b < 2; b++)
            #pragma unroll
            for (int c = 0; c < 4; c++) { accg[a][b][c] = 0.f; accu[a][b][c] = 0.f; }

    const float* wgB = Wg + (size_t)e * H_DIM * I_DIM + nt * 64;
    const float* wuB = Wu + (size_t)e * H_DIM * I_DIM + nt * 64;

    for (int ch = 0; ch < H_DIM / 64; ch++) {
        int k0 = ch * 64;
        // ---- A: 64 gathered token rows x 64 k, fp32 -> bf16 hi/lo ----
        #pragma unroll
        for (int it = 0; it < 4; it++) {
            int idx = tid + it * 256;
            int row = idx >> 4, cg = idx & 15;
            int tok = s_toks[row];
            float4 v = make_float4(0.f, 0.f, 0.f, 0.f);
            if (tok >= 0) v = *(const float4*)(x + (size_t)tok * H_DIM + k0 + cg * 4);
            uint32_t h0, l0, h1, l1;
            bsplit2(v.x, v.y, h0, l0);
            bsplit2(v.z, v.w, h1, l1);
            uint32_t o = SWZB((uint32_t)(row * 128 + cg * 8));
            *(uint2*)(Ahi + o) = make_uint2(h0, h1);
            *(uint2*)(Alo + o) = make_uint2(l0, l1);
        }
        // ---- B: Wg & Wu [k][n] -> smem [n][k] bf16 hi/lo ----
        #pragma unroll
        for (int mi = 0; mi < 2; mi++) {
            const float* WB = mi ? wuB : wgB;
            char* BH = mi ? Buh : Bgh;
            char* BL = mi ? Bul : Bgl;
            #pragma unroll
            for (int it = 0; it < 4; it++) {
                int c = tid + it * 256;        // 1024 cells: (kb 0..15, n 0..63)
                int kb = c >> 6, n = c & 63;
                const float* p = WB + (size_t)(k0 + kb * 4) * I_DIM + n;
                float w0 = p[0];
                float w1 = p[I_DIM];
                float w2 = p[2 * I_DIM];
                float w3 = p[3 * I_DIM];
                uint32_t h01, l01, h23, l23;
                bsplit2(w0, w1, h01, l01);
                bsplit2(w2, w3, h23, l23);
                uint32_t o = SWZB((uint32_t)(n * 128 + kb * 8));
                *(uint2*)(BH + o) = make_uint2(h01, h23);
                *(uint2*)(BL + o) = make_uint2(l01, l23);
            }
        }
        __syncthreads();

        // ---- MMA: 4 k16 steps ----
        #pragma unroll
        for (int ks = 0; ks < 4; ks++) {
            uint32_t ah[2][4], al[2][4];
            #pragma unroll
            for (int mf = 0; mf < 2; mf++) {
                uint32_t lin = (uint32_t)((aRow + mf * 16) * 128) + (uint32_t)(ks * 32) + aKb;
                uint32_t o = SWZB(lin);
                ldm4(ah[mf], uAhi + o);
                ldm4(al[mf], uAlo + o);
            }
            uint32_t blin = (uint32_t)(bRow * 128) + (uint32_t)(ks * 32) + bKb;
            uint32_t ob = SWZB(blin);
            uint32_t bgh[4], bgl[4], buh[4], bul[4];
            ldm4(bgh, uBgh + ob);
            ldm4(bgl, uBgl + ob);
            ldm4(buh, uBuh + ob);
            ldm4(bul, uBul + ob);
            #pragma unroll
            for (int mf = 0; mf < 2; mf++) {
                #pragma unroll
                for (int nf = 0; nf < 2; nf++) {
                    mma16816(accg[mf][nf], ah[mf], bgh[nf * 2], bgh[nf * 2 + 1]);
                    mma16816(accg[mf][nf], ah[mf], bgl[nf * 2], bgl[nf * 2 + 1]);
                    mma16816(accg[mf][nf], al[mf], bgh[nf * 2], bgh[nf * 2 + 1]);
                    mma16816(accu[mf][nf], ah[mf], buh[nf * 2], buh[nf * 2 + 1]);
                    mma16816(accu[mf][nf], ah[mf], bul[nf * 2], bul[nf * 2 + 1]);
                    mma16816(accu[mf][nf], al[mf], buh[nf * 2], buh[nf * 2 + 1]);
                }
            }
        }
        __syncthreads();
    }

    // ---- epilogue: a = silu(g) * u ----
    int lr = lane >> 2, lc = (lane & 3) * 2;
    #pragma unroll
    for (int mf = 0; mf < 2; mf++) {
        #pragma unroll
        for (int nf = 0; nf < 2; nf++) {
            int col = nt * 64 + wn * 16 + nf * 8 + lc;
            #pragma unroll
            for (int half = 0; half < 2; half++) {
                int row = wm * 32 + mf * 16 + lr + half * 8;
                if (m0 + row < ne) {
                    int rid = s_rids[row];
                    float g0 = accg[mf][nf][half * 2 + 0];
                    float g1 = accg[mf][nf][half * 2 + 1];
                    float u0 = accu[mf][nf][half * 2 + 0];
                    float u1 = accu[mf][nf][half * 2 + 1];
                    float2 o;
                    o.x = (g0 / (1.f + expf(-g0))) * u0;
                    o.y = (g1 / (1.f + expf(-g1))) * u1;
                    *(float2*)(g_abuf + (size_t)rid * I_DIM + col) = o;
                }
            }
        }
    }
}

// ---------------- kernel 4: down HMMA bf16 hi/lo ----------------
__global__ __launch_bounds__(256) void down_kernel(const float* __restrict__ Wd)
{
    const int nt = blockIdx.x;   // 16 (H / 64)
    const int mt = blockIdx.y;   // 4
    const int e  = blockIdx.z;   // 32
    int ne = g_cnt[e];
    int m0 = mt * 64;
    if (m0 >= ne) return;

    extern __shared__ __align__(128) char dsm[];
    char* Ahi = dsm;
    char* Alo = dsm + TILE_B;
    char* Bh  = dsm + 2 * TILE_B;
    char* Bl  = dsm + 3 * TILE_B;
    __shared__ int   s_rids[64];
    __shared__ float s_wts[64];

    int tid = threadIdx.x;
    int lane = tid & 31;
    int w = tid >> 5;
    int wm = w & 1;
    int wn = w >> 1;

    if (tid < 64) {
        int i = m0 + tid;
        if (i < ne) {
            int tk = g_tok[e * T_TOK + i];
            s_rids[tid] = tk * TOPK + g_slot[e * T_TOK + i];
            s_wts[tid]  = g_wt[e * T_TOK + i];
        } else { s_rids[tid] = -1; s_wts[tid] = 0.f; }
    }
    __syncthreads();

    uint32_t uAhi = smem_u32(Ahi), uAlo = smem_u32(Alo);
    uint32_t uBh = smem_u32(Bh), uBl = smem_u32(Bl);

    int aRow = wm * 32 + (lane & 15);
    uint32_t aKb = (uint32_t)((lane >> 4) * 16);
    int bRow = wn * 16 + (lane & 7) + ((lane >> 4) << 3);
    uint32_t bKb = (uint32_t)(((lane >> 3) & 1) * 16);

    float acc[2][2][4];
    #pragma unroll
    for (int a = 0; a < 2; a++)
        #pragma unroll
        for (int b = 0; b < 2; b++)
            #pragma unroll
            for (int c = 0; c < 4; c++) acc[a][b][c] = 0.f;

    const float* wdB = Wd + (size_t)e * I_DIM * H_DIM + nt * 64;

    for (int ch = 0; ch < I_DIM / 64; ch++) {
        int k0 = ch * 64;
        #pragma unroll
        for (int it = 0; it < 4; it++) {
            int idx = tid + it * 256;
            int row = idx >> 4, cg = idx & 15;
            int rid = s_rids[row];
            float4 v = make_float4(0.f, 0.f, 0.f, 0.f);
            if (rid >= 0) v = *(const float4*)(g_abuf + (size_t)rid * I_DIM + k0 + cg * 4);
            uint32_t h0, l0, h1, l1;
            bsplit2(v.x, v.y, h0, l0);
            bsplit2(v.z, v.w, h1, l1);
            uint32_t o = SWZB((uint32_t)(row * 128 + cg * 8));
            *(uint2*)(Ahi + o) = make_uint2(h0, h1);
            *(uint2*)(Alo + o) = make_uint2(l0, l1);
        }
        #pragma unroll
        for (int it = 0; it < 4; it++) {
            int c = tid + it * 256;
            int kb = c >> 6, n = c & 63;
            const float* p = wdB + (size_t)(k0 + kb * 4) * H_DIM + n;
            float w0 = p[0];
            float w1 = p[H_DIM];
            float w2 = p[2 * H_DIM];
            float w3 = p[3 * H_DIM];
            uint32_t h01, l01, h23, l23;
            bsplit2(w0, w1, h01, l01);
            bsplit2(w2, w3, h23, l23);
            uint32_t o = SWZB((uint32_t)(n * 128 + kb * 8));
            *(uint2*)(Bh + o) = make_uint2(h01, h23);
            *(uint2*)(Bl + o) = make_uint2(l01, l23);
        }
        __syncthreads();

        #pragma unroll
        for (int ks = 0; ks < 4; ks++) {
            uint32_t ah[2][4], al[2][4];
            #pragma unroll
            for (int mf = 0; mf < 2; mf++) {
                uint32_t lin = (uint32_t)((aRow + mf * 16) * 128) + (uint32_t)(ks * 32) + aKb;
                uint32_t o = SWZB(lin);
                ldm4(ah[mf], uAhi + o);
                ldm4(al[mf], uAlo + o);
            }
            uint32_t blin = (uint32_t)(bRow * 128) + (uint32_t)(ks * 32) + bKb;
            uint32_t ob = SWZB(blin);
            uint32_t bh[4], bl[4];
            ldm4(bh, uBh + ob);
            ldm4(bl, uBl + ob);
            #pragma unroll
            for (int mf = 0; mf < 2; mf++) {
                #pragma unroll
                for (int nf = 0; nf < 2; nf++) {
                    mma16816(acc[mf][nf], ah[mf], bh[nf * 2], bh[nf * 2 + 1]);
                    mma16816(acc[mf][nf], ah[mf], bl[nf * 2], bl[nf * 2 + 1]);
                    mma16816(acc[mf][nf], al[mf], bh[nf * 2], bh[nf * 2 + 1]);
                }
            }
        }
        __syncthreads();
    }

    int lr = lane >> 2, lc = (lane & 3) * 2;
    #pragma unroll
    for (int mf = 0; mf < 2; mf++) {
        #pragma unroll
        for (int nf = 0; nf < 2; nf++) {
            int col = nt * 64 + wn * 16 + nf * 8 + lc;
            #pragma unroll
            for (int half = 0; half < 2; half++) {
                int row = wm * 32 + mf * 16 + lr + half * 8;
                if (m0 + row < ne) {
                    int rid = s_rids[row];
                    float wt = s_wts[row];
                    float2 o;
                    o.x = wt * acc[mf][nf][half * 2 + 0];
                    o.y = wt * acc[mf][nf][half * 2 + 1];
                    *(float2*)(g_ybuf + (size_t)rid * H_DIM + col) = o;
                }
            }
        }
    }
}

// ---------------- kernel 5: deterministic combine ----------------
__global__ __launch_bounds__(256) void combine_kernel(float* __restrict__ out)
{
    int idx = blockIdx.x * 256 + threadIdx.x;
    int t = idx >> 10;
    int h = idx & 1023;
    float s = 0.f;
    #pragma unroll
    for (int k = 0; k < TOPK; k++)
        s += g_ybuf[((size_t)t * TOPK + k) * H_DIM + h];
    out[idx] = s;
}

// ---------------- launch ----------------
#define GATEUP_SMEM (6 * TILE_B)
#define DOWN_SMEM   (4 * TILE_B)

extern "C" void kernel_launch(void* const* d_in, const int* in_sizes, int n_in,
                              void* d_out, int out_size)
{
    const float* x      = (const float*)d_in[0];
    const float* gate_w = (const float*)d_in[1];
    const float* bias   = (const float*)d_in[2];
    const float* Wg     = (const float*)d_in[3];
    const float* Wu     = (const float*)d_in[4];
    const float* Wd     = (const float*)d_in[5];
    float* out = (float*)d_out;

    cudaFuncSetAttribute(gateup_kernel, cudaFuncAttributeMaxDynamicSharedMemorySize, GATEUP_SMEM);
    cudaFuncSetAttribute(down_kernel,   cudaFuncAttributeMaxDynamicSharedMemorySize, DOWN_SMEM);

    routing_kernel<<<T_TOK, 128>>>(x, gate_w, bias);
    build_lists_kernel<<<1, E_EXP>>>();
    gateup_kernel<<<dim3(I_DIM / 64, 4, E_EXP), 256, GATEUP_SMEM>>>(x, Wg, Wu);
    down_kernel<<<dim3(H_DIM / 64, 4, E_EXP), 256, DOWN_SMEM>>>(Wd);
    combine_kernel<<<(T_TOK * H_DIM) / 256, 256>>>(out);
}

// round 5
// speedup vs baseline: 4.5041x; 2.4052x over previous
#include <cuda_runtime.h>
#include <cuda_bf16.h>
#include <math.h>
#include <stdint.h>

#define T_TOK 256
#define H_DIM 1024
#define I_DIM 512
#define E_EXP 32
#define TOPK  8
#define NGRP  8
#define GSZ   4
#define TKG   4

#define SWZB(o) ((o) ^ (((o) >> 3) & 0x70))

// ---------------- helpers ----------------
__device__ __forceinline__ uint32_t smem_u32(const void* p) {
    uint32_t a;
    asm("{ .reg .u64 t; cvta.to.shared.u64 t, %1; cvt.u32.u64 %0, t; }" : "=r"(a) : "l"(p));
    return a;
}

// split 2 fp32 -> packed bf16x2 hi + bf16x2 lo (lo = exact residual)
__device__ __forceinline__ void bsplit2(float e0, float e1, uint32_t &h, uint32_t &l) {
    asm("cvt.rn.bf16x2.f32 %0, %1, %2;" : "=r"(h) : "f"(e1), "f"(e0));
    float f0 = __uint_as_float(h << 16);
    float f1 = __uint_as_float(h & 0xFFFF0000u);
    float r0 = e0 - f0, r1 = e1 - f1;
    asm("cvt.rn.bf16x2.f32 %0, %1, %2;" : "=r"(l) : "f"(r1), "f"(r0));
}

__device__ __forceinline__ void ldm4(uint32_t r[4], uint32_t addr) {
    asm volatile("ldmatrix.sync.aligned.m8n8.x4.shared.b16 {%0,%1,%2,%3}, [%4];"
        : "=r"(r[0]), "=r"(r[1]), "=r"(r[2]), "=r"(r[3]) : "r"(addr));
}

__device__ __forceinline__ void mma16816(float d[4], const uint32_t a[4],
                                         uint32_t b0, uint32_t b1) {
    asm volatile("mma.sync.aligned.m16n8k16.row.col.f32.bf16.bf16.f32 "
        "{%0,%1,%2,%3}, {%4,%5,%6,%7}, {%8,%9}, {%0,%1,%2,%3};"
        : "+f"(d[0]), "+f"(d[1]), "+f"(d[2]), "+f"(d[3])
        : "r"(a[0]), "r"(a[1]), "r"(a[2]), "r"(a[3]), "r"(b0), "r"(b1));
}

__device__ __forceinline__ void cpa16(uint32_t dst, const void* src, uint32_t sz) {
    asm volatile("cp.async.cg.shared.global [%0], [%1], 16, %2;"
        :: "r"(dst), "l"(src), "r"(sz) : "memory");
}
#define CPA_COMMIT() asm volatile("cp.async.commit_group;" ::: "memory")
#define CPA_WAIT0()  asm volatile("cp.async.wait_group 0;" ::: "memory")

// ---------------- device scratch ----------------
__device__ int   g_topk_idx[T_TOK * TOPK];
__device__ float g_topk_w[T_TOK * TOPK];
__device__ int   g_cnt[E_EXP];
__device__ int   g_tok[E_EXP * T_TOK];
__device__ int   g_slot[E_EXP * T_TOK];
__device__ float g_wt[E_EXP * T_TOK];
__device__ uint16_t g_xhi[T_TOK * H_DIM];
__device__ uint16_t g_xlo[T_TOK * H_DIM];
__device__ uint16_t g_ahi[T_TOK * TOPK * I_DIM];
__device__ uint16_t g_alo[T_TOK * TOPK * I_DIM];
__device__ float g_ybuf[T_TOK * TOPK * H_DIM];

// ---------------- kernel 0: split x into bf16 hi/lo ----------------
__global__ __launch_bounds__(256) void split_x_kernel(const float* __restrict__ x)
{
    int idx = blockIdx.x * 256 + threadIdx.x;   // T*H/4 threads
    float4 v = *(const float4*)(x + (size_t)idx * 4);
    uint32_t h0, l0, h1, l1;
    bsplit2(v.x, v.y, h0, l0);
    bsplit2(v.z, v.w, h1, l1);
    ((uint2*)g_xhi)[idx] = make_uint2(h0, h1);
    ((uint2*)g_xlo)[idx] = make_uint2(l0, l1);
}

// ---------------- kernel 1: routing ----------------
__global__ __launch_bounds__(128) void routing_kernel(
    const float* __restrict__ x, const float* __restrict__ gate_w,
    const float* __restrict__ bias)
{
    int t = blockIdx.x;
    __shared__ float xs[H_DIM];
    __shared__ float sc[E_EXP];
    __shared__ float sfc[E_EXP];
    int tid = threadIdx.x;
    for (int i = tid; i < H_DIM; i += 128) xs[i] = x[(size_t)t * H_DIM + i];
    __syncthreads();
    int warp = tid >> 5, lane = tid & 31;
    for (int e = warp; e < E_EXP; e += 4) {
        float s = 0.f;
        for (int h = lane; h < H_DIM; h += 32)
            s += xs[h] * gate_w[(size_t)h * E_EXP + e];
        #pragma unroll
        for (int o = 16; o; o >>= 1) s += __shfl_xor_sync(0xffffffffu, s, o);
        if (lane == 0) {
            float sig = 1.f / (1.f + expf(-s));
            sc[e] = sig;
            sfc[e] = sig + bias[e];
        }
    }
    __syncthreads();
    if (tid == 0) {
        float gs[NGRP];
        #pragma unroll
        for (int g = 0; g < NGRP; g++) {
            float m1 = -1e30f, m2 = -1e30f;
            #pragma unroll
            for (int j = 0; j < GSZ; j++) {
                float v = sfc[g * GSZ + j];
                if (v > m1) { m2 = m1; m1 = v; }
                else if (v > m2) { m2 = v; }
            }
            gs[g] = m1 + m2;
        }
        bool gsel[NGRP];
        #pragma unroll
        for (int g = 0; g < NGRP; g++) gsel[g] = false;
        for (int r = 0; r < TKG; r++) {
            int b = -1;
            for (int g = 0; g < NGRP; g++)
                if (!gsel[g] && (b < 0 || gs[g] > gs[b])) b = g;
            gsel[b] = true;
        }
        float masked[E_EXP];
        bool used[E_EXP];
        #pragma unroll
        for (int e = 0; e < E_EXP; e++) {
            masked[e] = gsel[e >> 2] ? sfc[e] : 0.0f;
            used[e] = false;
        }
        int idx[TOPK];
        float wsum = 0.f;
        for (int r = 0; r < TOPK; r++) {
            int b = -1;
            for (int e = 0; e < E_EXP; e++)
                if (!used[e] && (b < 0 || masked[e] > masked[b])) b = e;
            used[b] = true;
            idx[r] = b;
            wsum += sc[b];
        }
        float scale = 2.5f / (wsum + 1e-20f);
        for (int r = 0; r < TOPK; r++) {
            g_topk_idx[t * TOPK + r] = idx[r];
            g_topk_w[t * TOPK + r]   = sc[idx[r]] * scale;
        }
    }
}

// ---------------- kernel 2: warp-per-expert ballot compaction ----------------
__global__ __launch_bounds__(1024) void build_lists_kernel()
{
    int e = threadIdx.x >> 5;
    int lane = threadIdx.x & 31;
    int cnt = 0;
    for (int t0 = 0; t0 < T_TOK; t0 += 32) {
        int t = t0 + lane;
        int found = -1;
        #pragma unroll
        for (int k = 0; k < TOPK; k++)
            if (g_topk_idx[t * TOPK + k] == e) found = k;
        unsigned m = __ballot_sync(0xffffffffu, found >= 0);
        if (found >= 0) {
            int pos = cnt + __popc(m & ((1u << lane) - 1));
            g_tok [e * T_TOK + pos] = t;
            g_slot[e * T_TOK + pos] = found;
            g_wt  [e * T_TOK + pos] = g_topk_w[t * TOPK + found];
        }
        cnt += __popc(m);
    }
    if (lane == 0) g_cnt[e] = cnt;
}

// ---------------- GEMM kernels ----------------
// CTA 64x64, K chunk 64, 8 warps (warp tile 32x16), SW128 smem, A bf16 hi/lo via
// cp.async double-buffered, B fp32 register-prefetch -> split -> STS.

__global__ __launch_bounds__(256) void gateup_kernel(
    const float* __restrict__ Wg,
    const float* __restrict__ Wu)
{
    const int nt = blockIdx.x;   // 8
    const int mt = blockIdx.y;   // 4
    const int e  = blockIdx.z;   // 32
    int ne = g_cnt[e];
    int m0 = mt * 64;
    if (m0 >= ne) return;

    extern __shared__ __align__(128) char dsm[];
    // layout: A bufs [0,32K) : {AH0,AL0,AH1,AL1} each 8KB; B [32K,64K)
    char* Bgh = dsm + 32768;
    char* Bgl = dsm + 40960;
    char* Buh = dsm + 49152;
    char* Bul = dsm + 57344;
    __shared__ int s_toks[64];
    __shared__ int s_rids[64];

    int tid = threadIdx.x;
    int lane = tid & 31;
    int w = tid >> 5;
    int wm = w & 1;
    int wn = w >> 1;

    if (tid < 64) {
        int i = m0 + tid;
        if (i < ne) {
            int tk = g_tok[e * T_TOK + i];
            s_toks[tid] = tk;
            s_rids[tid] = tk * TOPK + g_slot[e * T_TOK + i];
        } else { s_toks[tid] = -1; s_rids[tid] = -1; }
    }
    __syncthreads();

    uint32_t uA = smem_u32(dsm);
    uint32_t uBgh = smem_u32(Bgh), uBgl = smem_u32(Bgl);
    uint32_t uBuh = smem_u32(Buh), uBul = smem_u32(Bul);

    // ---- A cp.async addressing (fixed per thread) ----
    int arow0 = tid >> 3, aseg = tid & 7;
    int arow1 = arow0 + 32;
    int tokA = s_toks[arow0], tokB = s_toks[arow1];
    const char* sH0 = (const char*)g_xhi + ((size_t)(tokA < 0 ? 0 : tokA) * H_DIM) * 2 + aseg * 16;
    const char* sH1 = (const char*)g_xhi + ((size_t)(tokB < 0 ? 0 : tokB) * H_DIM) * 2 + aseg * 16;
    const char* sL0 = (const char*)g_xlo + ((size_t)(tokA < 0 ? 0 : tokA) * H_DIM) * 2 + aseg * 16;
    const char* sL1 = (const char*)g_xlo + ((size_t)(tokB < 0 ? 0 : tokB) * H_DIM) * 2 + aseg * 16;
    uint32_t szA = (tokA >= 0) ? 16u : 0u;
    uint32_t szB = (tokB >= 0) ? 16u : 0u;
    uint32_t dO0 = SWZB((uint32_t)(arow0 * 128 + aseg * 16));
    uint32_t dO1 = SWZB((uint32_t)(arow1 * 128 + aseg * 16));

    // ldmatrix addressing
    int aRow = wm * 32 + (lane & 15);
    uint32_t aKb = (uint32_t)((lane >> 4) * 16);
    int bRow = wn * 16 + (lane & 7) + ((lane >> 4) << 3);
    uint32_t bKb = (uint32_t)(((lane >> 3) & 1) * 16);
    uint32_t obase = SWZB((uint32_t)(bRow * 128) + bKb);  // + ks*32 applied pre-swizzle

    float accg[2][2][4], accu[2][2][4];
    #pragma unroll
    for (int a = 0; a < 2; a++)
        #pragma unroll
        for (int b = 0; b < 2; b++)
            #pragma unroll
            for (int c = 0; c < 4; c++) { accg[a][b][c] = 0.f; accu[a][b][c] = 0.f; }

    const float* wgB = Wg + (size_t)e * H_DIM * I_DIM + nt * 64;
    const float* wuB = Wu + (size_t)e * H_DIM * I_DIM + nt * 64;

    // B register prefetch state
    float bw[2][4][4];
    int pkb = tid >> 6, pn = tid & 63;   // per-it layout: c = tid + it*256

    // prefetch B(0), issue A(0)
    #pragma unroll
    for (int mi = 0; mi < 2; mi++) {
        const float* WB = mi ? wuB : wgB;
        #pragma unroll
        for (int it = 0; it < 4; it++) {
            const float* p = WB + (size_t)((pkb + it * 4) * 4) * I_DIM + pn;
            bw[mi][it][0] = p[0];
            bw[mi][it][1] = p[I_DIM];
            bw[mi][it][2] = p[2 * I_DIM];
            bw[mi][it][3] = p[3 * I_DIM];
        }
    }
    cpa16(uA + dO0, sH0, szA);
    cpa16(uA + dO1, sH1, szA ? szB : szB);
    cpa16(uA + 8192 + dO0, sL0, szA);
    cpa16(uA + 8192 + dO1, sL1, szB);
    CPA_COMMIT();

    const int NCH = H_DIM / 64;  // 16
    for (int ch = 0; ch < NCH; ch++) {
        CPA_WAIT0();
        // store B(ch) from regs
        #pragma unroll
        for (int mi = 0; mi < 2; mi++) {
            char* BH = mi ? Buh : Bgh;
            char* BL = mi ? Bul : Bgl;
            #pragma unroll
            for (int it = 0; it < 4; it++) {
                uint32_t h01, l01, h23, l23;
                bsplit2(bw[mi][it][0], bw[mi][it][1], h01, l01);
                bsplit2(bw[mi][it][2], bw[mi][it][3], h23, l23);
                uint32_t o = SWZB((uint32_t)(pn * 128 + (pkb + it * 4) * 8));
                *(uint2*)(BH + o) = make_uint2(h01, h23);
                *(uint2*)(BL + o) = make_uint2(l01, l23);
            }
        }
        __syncthreads();

        if (ch + 1 < NCH) {
            // issue A(ch+1) into alt buffer
            uint32_t ab = uA + (uint32_t)(((ch + 1) & 1) * 16384);
            uint32_t boff = (uint32_t)((ch + 1) * 128);
            cpa16(ab + dO0, sH0 + boff, szA);
            cpa16(ab + dO1, sH1 + boff, szB);
            cpa16(ab + 8192 + dO0, sL0 + boff, szA);
            cpa16(ab + 8192 + dO1, sL1 + boff, szB);
            CPA_COMMIT();
            // prefetch B(ch+1)
            int k0n = (ch + 1) * 64;
            #pragma unroll
            for (int mi = 0; mi < 2; mi++) {
                const float* WB = mi ? wuB : wgB;
                #pragma unroll
                for (int it = 0; it < 4; it++) {
                    const float* p = WB + (size_t)(k0n + (pkb + it * 4) * 4) * I_DIM + pn;
                    bw[mi][it][0] = p[0];
                    bw[mi][it][1] = p[I_DIM];
                    bw[mi][it][2] = p[2 * I_DIM];
                    bw[mi][it][3] = p[3 * I_DIM];
                }
            }
        }

        uint32_t uAhi = uA + (uint32_t)((ch & 1) * 16384);
        uint32_t uAlo = uAhi + 8192;
        #pragma unroll
        for (int ks = 0; ks < 4; ks++) {
            uint32_t ah[2][4], al[2][4];
            #pragma unroll
            for (int mf = 0; mf < 2; mf++) {
                uint32_t lin = (uint32_t)((aRow + mf * 16) * 128) + (uint32_t)(ks * 32) + aKb;
                uint32_t o = SWZB(lin);
                ldm4(ah[mf], uAhi + o);
                ldm4(al[mf], uAlo + o);
            }
            uint32_t ob = SWZB((uint32_t)(bRow * 128) + (uint32_t)(ks * 32) + bKb);
            uint32_t bgh[4], bgl[4], buh[4], bul[4];
            ldm4(bgh, uBgh + ob);
            ldm4(bgl, uBgl + ob);
            ldm4(buh, uBuh + ob);
            ldm4(bul, uBul + ob);
            #pragma unroll
            for (int mf = 0; mf < 2; mf++) {
                #pragma unroll
                for (int nf = 0; nf < 2; nf++) {
                    mma16816(accg[mf][nf], ah[mf], bgh[nf * 2], bgh[nf * 2 + 1]);
                    mma16816(accg[mf][nf], ah[mf], bgl[nf * 2], bgl[nf * 2 + 1]);
                    mma16816(accg[mf][nf], al[mf], bgh[nf * 2], bgh[nf * 2 + 1]);
                    mma16816(accu[mf][nf], ah[mf], buh[nf * 2], buh[nf * 2 + 1]);
                    mma16816(accu[mf][nf], ah[mf], bul[nf * 2], bul[nf * 2 + 1]);
                    mma16816(accu[mf][nf], al[mf], buh[nf * 2], buh[nf * 2 + 1]);
                }
            }
        }
        __syncthreads();
    }

    // epilogue: a = silu(g)*u, split to bf16 hi/lo
    int lr = lane >> 2, lc = (lane & 3) * 2;
    #pragma unroll
    for (int mf = 0; mf < 2; mf++) {
        #pragma unroll
        for (int nf = 0; nf < 2; nf++) {
            int col = nt * 64 + wn * 16 + nf * 8 + lc;
            #pragma unroll
            for (int half = 0; half < 2; half++) {
                int row = wm * 32 + mf * 16 + lr + half * 8;
                if (m0 + row < ne) {
                    int rid = s_rids[row];
                    float g0 = accg[mf][nf][half * 2 + 0];
                    float g1 = accg[mf][nf][half * 2 + 1];
                    float u0 = accu[mf][nf][half * 2 + 0];
                    float u1 = accu[mf][nf][half * 2 + 1];
                    float a0 = (g0 / (1.f + expf(-g0))) * u0;
                    float a1 = (g1 / (1.f + expf(-g1))) * u1;
                    uint32_t h, l;
                    bsplit2(a0, a1, h, l);
                    size_t off = (size_t)rid * I_DIM + col;
                    *(uint32_t*)(g_ahi + off) = h;
                    *(uint32_t*)(g_alo + off) = l;
                }
            }
        }
    }
}

__global__ __launch_bounds__(256) void down_kernel(const float* __restrict__ Wd)
{
    const int nt = blockIdx.x;   // 16
    const int mt = blockIdx.y;   // 4
    const int e  = blockIdx.z;   // 32
    int ne = g_cnt[e];
    int m0 = mt * 64;
    if (m0 >= ne) return;

    extern __shared__ __align__(128) char dsm[];
    char* Bh = dsm + 32768;
    char* Bl = dsm + 40960;
    __shared__ int   s_rids[64];
    __shared__ float s_wts[64];

    int tid = threadIdx.x;
    int lane = tid & 31;
    int w = tid >> 5;
    int wm = w & 1;
    int wn = w >> 1;

    if (tid < 64) {
        int i = m0 + tid;
        if (i < ne) {
            int tk = g_tok[e * T_TOK + i];
            s_rids[tid] = tk * TOPK + g_slot[e * T_TOK + i];
            s_wts[tid]  = g_wt[e * T_TOK + i];
        } else { s_rids[tid] = -1; s_wts[tid] = 0.f; }
    }
    __syncthreads();

    uint32_t uA = smem_u32(dsm);
    uint32_t uBh = smem_u32(Bh), uBl = smem_u32(Bl);

    int arow0 = tid >> 3, aseg = tid & 7;
    int arow1 = arow0 + 32;
    int ridA = s_rids[arow0], ridB = s_rids[arow1];
    const char* sH0 = (const char*)g_ahi + ((size_t)(ridA < 0 ? 0 : ridA) * I_DIM) * 2 + aseg * 16;
    const char* sH1 = (const char*)g_ahi + ((size_t)(ridB < 0 ? 0 : ridB) * I_DIM) * 2 + aseg * 16;
    const char* sL0 = (const char*)g_alo + ((size_t)(ridA < 0 ? 0 : ridA) * I_DIM) * 2 + aseg * 16;
    const char* sL1 = (const char*)g_alo + ((size_t)(ridB < 0 ? 0 : ridB) * I_DIM) * 2 + aseg * 16;
    uint32_t szA = (ridA >= 0) ? 16u : 0u;
    uint32_t szB = (ridB >= 0) ? 16u : 0u;
    uint32_t dO0 = SWZB((uint32_t)(arow0 * 128 + aseg * 16));
    uint32_t dO1 = SWZB((uint32_t)(arow1 * 128 + aseg * 16));

    int aRow = wm * 32 + (lane & 15);
    uint32_t aKb = (uint32_t)((lane >> 4) * 16);
    int bRow = wn * 16 + (lane & 7) + ((lane >> 4) << 3);
    uint32_t bKb = (uint32_t)(((lane >> 3) & 1) * 16);

    float acc[2][2][4];
    #pragma unroll
    for (int a = 0; a < 2; a++)
        #pragma unroll
        for (int b = 0; b < 2; b++)
            #pragma unroll
            for (int c = 0; c < 4; c++) acc[a][b][c] = 0.f;

    const float* wdB = Wd + (size_t)e * I_DIM * H_DIM + nt * 64;
    float bw[4][4];
    int pkb = tid >> 6, pn = tid & 63;

    #pragma unroll
    for (int it = 0; it < 4; it++) {
        const float* p = wdB + (size_t)((pkb + it * 4) * 4) * H_DIM + pn;
        bw[it][0] = p[0];
        bw[it][1] = p[H_DIM];
        bw[it][2] = p[2 * H_DIM];
        bw[it][3] = p[3 * H_DIM];
    }
    cpa16(uA + dO0, sH0, szA);
    cpa16(uA + dO1, sH1, szB);
    cpa16(uA + 8192 + dO0, sL0, szA);
    cpa16(uA + 8192 + dO1, sL1, szB);
    CPA_COMMIT();

    const int NCH = I_DIM / 64;  // 8
    for (int ch = 0; ch < NCH; ch++) {
        CPA_WAIT0();
        #pragma unroll
        for (int it = 0; it < 4; it++) {
            uint32_t h01, l01, h23, l23;
            bsplit2(bw[it][0], bw[it][1], h01, l01);
            bsplit2(bw[it][2], bw[it][3], h23, l23);
            uint32_t o = SWZB((uint32_t)(pn * 128 + (pkb + it * 4) * 8));
            *(uint2*)(Bh + o) = make_uint2(h01, h23);
            *(uint2*)(Bl + o) = make_uint2(l01, l23);
        }
        __syncthreads();

        if (ch + 1 < NCH) {
            uint32_t ab = uA + (uint32_t)(((ch + 1) & 1) * 16384);
            uint32_t boff = (uint32_t)((ch + 1) * 128);
            cpa16(ab + dO0, sH0 + boff, szA);
            cpa16(ab + dO1, sH1 + boff, szB);
            cpa16(ab + 8192 + dO0, sL0 + boff, szA);
            cpa16(ab + 8192 + dO1, sL1 + boff, szB);
            CPA_COMMIT();
            int k0n = (ch + 1) * 64;
            #pragma unroll
            for (int it = 0; it < 4; it++) {
                const float* p = wdB + (size_t)(k0n + (pkb + it * 4) * 4) * H_DIM + pn;
                bw[it][0] = p[0];
                bw[it][1] = p[H_DIM];
                bw[it][2] = p[2 * H_DIM];
                bw[it][3] = p[3 * H_DIM];
            }
        }

        uint32_t uAhi = uA + (uint32_t)((ch & 1) * 16384);
        uint32_t uAlo = uAhi + 8192;
        #pragma unroll
        for (int ks = 0; ks < 4; ks++) {
            uint32_t ah[2][4], al[2][4];
            #pragma unroll
            for (int mf = 0; mf < 2; mf++) {
                uint32_t lin = (uint32_t)((aRow + mf * 16) * 128) + (uint32_t)(ks * 32) + aKb;
                uint32_t o = SWZB(lin);
                ldm4(ah[mf], uAhi + o);
                ldm4(al[mf], uAlo + o);
            }
            uint32_t ob = SWZB((uint32_t)(bRow * 128) + (uint32_t)(ks * 32) + bKb);
            uint32_t bh[4], bl[4];
            ldm4(bh, uBh + ob);
            ldm4(bl, uBl + ob);
            #pragma unroll
            for (int mf = 0; mf < 2; mf++) {
                #pragma unroll
                for (int nf = 0; nf < 2; nf++) {
                    mma16816(acc[mf][nf], ah[mf], bh[nf * 2], bh[nf * 2 + 1]);
                    mma16816(acc[mf][nf], ah[mf], bl[nf * 2], bl[nf * 2 + 1]);
                    mma16816(acc[mf][nf], al[mf], bh[nf * 2], bh[nf * 2 + 1]);
                }
            }
        }
        __syncthreads();
    }

    int lr = lane >> 2, lc = (lane & 3) * 2;
    #pragma unroll
    for (int mf = 0; mf < 2; mf++) {
        #pragma unroll
        for (int nf = 0; nf < 2; nf++) {
            int col = nt * 64 + wn * 16 + nf * 8 + lc;
            #pragma unroll
            for (int half = 0; half < 2; half++) {
                int row = wm * 32 + mf * 16 + lr + half * 8;
                if (m0 + row < ne) {
                    int rid = s_rids[row];
                    float wt = s_wts[row];
                    float2 o;
                    o.x = wt * acc[mf][nf][half * 2 + 0];
                    o.y = wt * acc[mf][nf][half * 2 + 1];
                    *(float2*)(g_ybuf + (size_t)rid * H_DIM + col) = o;
                }
            }
        }
    }
}

// ---------------- kernel 5: deterministic combine ----------------
__global__ __launch_bounds__(256) void combine_kernel(float* __restrict__ out)
{
    int idx = blockIdx.x * 256 + threadIdx.x;
    int t = idx >> 10;
    int h = idx & 1023;
    float s = 0.f;
    #pragma unroll
    for (int k = 0; k < TOPK; k++)
        s += g_ybuf[((size_t)t * TOPK + k) * H_DIM + h];
    out[idx] = s;
}

// ---------------- launch ----------------
#define GATEUP_SMEM 65536
#define DOWN_SMEM   49152

extern "C" void kernel_launch(void* const* d_in, const int* in_sizes, int n_in,
                              void* d_out, int out_size)
{
    const float* x      = (const float*)d_in[0];
    const float* gate_w = (const float*)d_in[1];
    const float* bias   = (const float*)d_in[2];
    const float* Wg     = (const float*)d_in[3];
    const float* Wu     = (const float*)d_in[4];
    const float* Wd     = (const float*)d_in[5];
    float* out = (float*)d_out;

    cudaFuncSetAttribute(gateup_kernel, cudaFuncAttributeMaxDynamicSharedMemorySize, GATEUP_SMEM);
    cudaFuncSetAttribute(down_kernel,   cudaFuncAttributeMaxDynamicSharedMemorySize, DOWN_SMEM);

    split_x_kernel<<<(T_TOK * H_DIM / 4) / 256, 256>>>(x);
    routing_kernel<<<T_TOK, 128>>>(x, gate_w, bias);
    build_lists_kernel<<<1, 1024>>>();
    gateup_kernel<<<dim3(I_DIM / 64, 4, E_EXP), 256, GATEUP_SMEM>>>(Wg, Wu);
    down_kernel<<<dim3(H_DIM / 64, 4, E_EXP), 256, DOWN_SMEM>>>(Wd);
    combine_kernel<<<(T_TOK * H_DIM) / 256, 256>>>(out);
}

// round 6
// speedup vs baseline: 4.5233x; 1.0043x over previous
#include <cuda_runtime.h>
#include <cuda_bf16.h>
#include <math.h>
#include <stdint.h>

#define T_TOK 256
#define H_DIM 1024
#define I_DIM 512
#define E_EXP 32
#define TOPK  8
#define NGRP  8
#define GSZ   4
#define TKG   4

#define SWZB(o) ((o) ^ (((o) >> 3) & 0x70))

// ---------------- helpers ----------------
__device__ __forceinline__ uint32_t smem_u32(const void* p) {
    uint32_t a;
    asm("{ .reg .u64 t; cvta.to.shared.u64 t, %1; cvt.u32.u64 %0, t; }" : "=r"(a) : "l"(p));
    return a;
}

// split 2 fp32 -> packed bf16x2 hi + bf16x2 lo (lo = exact residual)
__device__ __forceinline__ void bsplit2(float e0, float e1, uint32_t &h, uint32_t &l) {
    asm("cvt.rn.bf16x2.f32 %0, %1, %2;" : "=r"(h) : "f"(e1), "f"(e0));
    float f0 = __uint_as_float(h << 16);
    float f1 = __uint_as_float(h & 0xFFFF0000u);
    float r0 = e0 - f0, r1 = e1 - f1;
    asm("cvt.rn.bf16x2.f32 %0, %1, %2;" : "=r"(l) : "f"(r1), "f"(r0));
}

__device__ __forceinline__ void ldm4(uint32_t r[4], uint32_t addr) {
    asm volatile("ldmatrix.sync.aligned.m8n8.x4.shared.b16 {%0,%1,%2,%3}, [%4];"
        : "=r"(r[0]), "=r"(r[1]), "=r"(r[2]), "=r"(r[3]) : "r"(addr));
}

__device__ __forceinline__ void mma16816(float d[4], const uint32_t a[4],
                                         uint32_t b0, uint32_t b1) {
    asm volatile("mma.sync.aligned.m16n8k16.row.col.f32.bf16.bf16.f32 "
        "{%0,%1,%2,%3}, {%4,%5,%6,%7}, {%8,%9}, {%0,%1,%2,%3};"
        : "+f"(d[0]), "+f"(d[1]), "+f"(d[2]), "+f"(d[3])
        : "r"(a[0]), "r"(a[1]), "r"(a[2]), "r"(a[3]), "r"(b0), "r"(b1));
}

__device__ __forceinline__ void cpa16(uint32_t dst, const void* src, uint32_t sz) {
    asm volatile("cp.async.cg.shared.global [%0], [%1], 16, %2;"
        :: "r"(dst), "l"(src), "r"(sz) : "memory");
}
#define CPA_COMMIT() asm volatile("cp.async.commit_group;" ::: "memory")
#define CPA_WAIT0()  asm volatile("cp.async.wait_group 0;" ::: "memory")

// ---------------- device scratch ----------------
__device__ int   g_topk_idx[T_TOK * TOPK];
__device__ float g_topk_w[T_TOK * TOPK];
__device__ int   g_cnt[E_EXP];
__device__ int   g_tok[E_EXP * T_TOK];
__device__ int   g_slot[E_EXP * T_TOK];
__device__ float g_wt[E_EXP * T_TOK];
__device__ uint16_t g_xhi[T_TOK * H_DIM];
__device__ uint16_t g_xlo[T_TOK * H_DIM];
__device__ uint16_t g_ahi[T_TOK * TOPK * I_DIM];
__device__ uint16_t g_alo[T_TOK * TOPK * I_DIM];
__device__ float g_ybuf[T_TOK * TOPK * H_DIM];

// ---------------- kernel 1: routing (+ fused x split) ----------------
__global__ __launch_bounds__(128) void routing_kernel(
    const float* __restrict__ x, const float* __restrict__ gate_w,
    const float* __restrict__ bias)
{
    int t = blockIdx.x;
    __shared__ float xs[H_DIM];
    __shared__ float sc[E_EXP];
    __shared__ float sfc[E_EXP];
    int tid = threadIdx.x;
    for (int i = tid; i < H_DIM / 4; i += 128) {
        float4 v = *(const float4*)(x + (size_t)t * H_DIM + i * 4);
        *(float4*)&xs[i * 4] = v;
        uint32_t h0, l0, h1, l1;
        bsplit2(v.x, v.y, h0, l0);
        bsplit2(v.z, v.w, h1, l1);
        ((uint2*)(g_xhi + (size_t)t * H_DIM))[i] = make_uint2(h0, h1);
        ((uint2*)(g_xlo + (size_t)t * H_DIM))[i] = make_uint2(l0, l1);
    }
    __syncthreads();
    int warp = tid >> 5, lane = tid & 31;
    for (int e = warp; e < E_EXP; e += 4) {
        float s = 0.f;
        for (int h = lane; h < H_DIM; h += 32)
            s += xs[h] * gate_w[(size_t)h * E_EXP + e];
        #pragma unroll
        for (int o = 16; o; o >>= 1) s += __shfl_xor_sync(0xffffffffu, s, o);
        if (lane == 0) {
            float sig = 1.f / (1.f + expf(-s));
            sc[e] = sig;
            sfc[e] = sig + bias[e];
        }
    }
    __syncthreads();
    if (tid == 0) {
        float gs[NGRP];
        #pragma unroll
        for (int g = 0; g < NGRP; g++) {
            float m1 = -1e30f, m2 = -1e30f;
            #pragma unroll
            for (int j = 0; j < GSZ; j++) {
                float v = sfc[g * GSZ + j];
                if (v > m1) { m2 = m1; m1 = v; }
                else if (v > m2) { m2 = v; }
            }
            gs[g] = m1 + m2;
        }
        bool gsel[NGRP];
        #pragma unroll
        for (int g = 0; g < NGRP; g++) gsel[g] = false;
        for (int r = 0; r < TKG; r++) {
            int b = -1;
            for (int g = 0; g < NGRP; g++)
                if (!gsel[g] && (b < 0 || gs[g] > gs[b])) b = g;
            gsel[b] = true;
        }
        float masked[E_EXP];
        bool used[E_EXP];
        #pragma unroll
        for (int e = 0; e < E_EXP; e++) {
            masked[e] = gsel[e >> 2] ? sfc[e] : 0.0f;
            used[e] = false;
        }
        int idx[TOPK];
        float wsum = 0.f;
        for (int r = 0; r < TOPK; r++) {
            int b = -1;
            for (int e = 0; e < E_EXP; e++)
                if (!used[e] && (b < 0 || masked[e] > masked[b])) b = e;
            used[b] = true;
            idx[r] = b;
            wsum += sc[b];
        }
        float scale = 2.5f / (wsum + 1e-20f);
        for (int r = 0; r < TOPK; r++) {
            g_topk_idx[t * TOPK + r] = idx[r];
            g_topk_w[t * TOPK + r]   = sc[idx[r]] * scale;
        }
    }
}

// ---------------- kernel 2: warp-per-expert ballot compaction ----------------
__global__ __launch_bounds__(1024) void build_lists_kernel()
{
    int e = threadIdx.x >> 5;
    int lane = threadIdx.x & 31;
    int cnt = 0;
    for (int t0 = 0; t0 < T_TOK; t0 += 32) {
        int t = t0 + lane;
        int found = -1;
        #pragma unroll
        for (int k = 0; k < TOPK; k++)
            if (g_topk_idx[t * TOPK + k] == e) found = k;
        unsigned m = __ballot_sync(0xffffffffu, found >= 0);
        if (found >= 0) {
            int pos = cnt + __popc(m & ((1u << lane) - 1));
            g_tok [e * T_TOK + pos] = t;
            g_slot[e * T_TOK + pos] = found;
            g_wt  [e * T_TOK + pos] = g_topk_w[t * TOPK + found];
        }
        cnt += __popc(m);
    }
    if (lane == 0) g_cnt[e] = cnt;
}

// ---------------- GEMM kernels ----------------
// CTA 64x64, K chunk 64, 8 warps (warp tile 32x16), SW128 smem.
// A bf16 hi/lo via cp.async double-buffered; B fp32 reg-prefetch -> split ->
// STS into DOUBLE-BUFFERED smem; single __syncthreads per chunk.

__global__ __launch_bounds__(256, 2) void gateup_kernel(
    const float* __restrict__ Wg,
    const float* __restrict__ Wu)
{
    const int nt = blockIdx.x;   // 8
    const int mt = blockIdx.y;   // 4
    const int e  = blockIdx.z;   // 32
    int ne = g_cnt[e];
    int m0 = mt * 64;
    if (m0 >= ne) return;

    extern __shared__ __align__(128) char dsm[];
    // A: [0,32K): {A0h,A0l,A1h,A1l} 8KB each
    // B: [32K,96K): buf0 {gh,gl,uh,ul} 8KB each, buf1 same at +32K
    __shared__ int s_toks[64];
    __shared__ int s_rids[64];

    int tid = threadIdx.x;
    int lane = tid & 31;
    int w = tid >> 5;
    int wm = w & 1;
    int wn = w >> 1;

    if (tid < 64) {
        int i = m0 + tid;
        if (i < ne) {
            int tk = g_tok[e * T_TOK + i];
            s_toks[tid] = tk;
            s_rids[tid] = tk * TOPK + g_slot[e * T_TOK + i];
        } else { s_toks[tid] = -1; s_rids[tid] = -1; }
    }
    __syncthreads();

    uint32_t uA = smem_u32(dsm);
    uint32_t uB = uA + 32768;

    // ---- A cp.async addressing ----
    int arow0 = tid >> 3, aseg = tid & 7;
    int arow1 = arow0 + 32;
    int tokA = s_toks[arow0], tokB = s_toks[arow1];
    const char* sH0 = (const char*)g_xhi + ((size_t)(tokA < 0 ? 0 : tokA) * H_DIM) * 2 + aseg * 16;
    const char* sH1 = (const char*)g_xhi + ((size_t)(tokB < 0 ? 0 : tokB) * H_DIM) * 2 + aseg * 16;
    const char* sL0 = (const char*)g_xlo + ((size_t)(tokA < 0 ? 0 : tokA) * H_DIM) * 2 + aseg * 16;
    const char* sL1 = (const char*)g_xlo + ((size_t)(tokB < 0 ? 0 : tokB) * H_DIM) * 2 + aseg * 16;
    uint32_t szA = (tokA >= 0) ? 16u : 0u;
    uint32_t szB = (tokB >= 0) ? 16u : 0u;
    uint32_t dO0 = SWZB((uint32_t)(arow0 * 128 + aseg * 16));
    uint32_t dO1 = SWZB((uint32_t)(arow1 * 128 + aseg * 16));

    // ldmatrix addressing
    int aRow = wm * 32 + (lane & 15);
    uint32_t aKb = (uint32_t)((lane >> 4) * 16);
    int bRow = wn * 16 + (lane & 7) + ((lane >> 4) << 3);
    uint32_t bKb = (uint32_t)(((lane >> 3) & 1) * 16);

    float accg[2][2][4], accu[2][2][4];
    #pragma unroll
    for (int a = 0; a < 2; a++)
        #pragma unroll
        for (int b = 0; b < 2; b++)
            #pragma unroll
            for (int c = 0; c < 4; c++) { accg[a][b][c] = 0.f; accu[a][b][c] = 0.f; }

    const float* wgB = Wg + (size_t)e * H_DIM * I_DIM + nt * 64;
    const float* wuB = Wu + (size_t)e * H_DIM * I_DIM + nt * 64;

    float bw[2][4][4];
    int pkb = tid >> 6, pn = tid & 63;

    // prologue: B(0)->regs, A(0)->buf0
    #pragma unroll
    for (int mi = 0; mi < 2; mi++) {
        const float* WB = mi ? wuB : wgB;
        #pragma unroll
        for (int it = 0; it < 4; it++) {
            const float* p = WB + (size_t)((pkb + it * 4) * 4) * I_DIM + pn;
            bw[mi][it][0] = p[0];
            bw[mi][it][1] = p[I_DIM];
            bw[mi][it][2] = p[2 * I_DIM];
            bw[mi][it][3] = p[3 * I_DIM];
        }
    }
    cpa16(uA + dO0, sH0, szA);
    cpa16(uA + dO1, sH1, szB);
    cpa16(uA + 8192 + dO0, sL0, szA);
    cpa16(uA + 8192 + dO1, sL1, szB);
    CPA_COMMIT();

    const int NCH = H_DIM / 64;  // 16
    for (int ch = 0; ch < NCH; ch++) {
        uint32_t bsel = (uint32_t)((ch & 1) * 32768);
        CPA_WAIT0();
        // store B(ch) regs -> smem buf(ch&1)
        {
            char* base = dsm + 32768 + (ch & 1) * 32768;
            #pragma unroll
            for (int mi = 0; mi < 2; mi++) {
                char* BH = base + mi * 16384;
                char* BL = BH + 8192;
                #pragma unroll
                for (int it = 0; it < 4; it++) {
                    uint32_t h01, l01, h23, l23;
                    bsplit2(bw[mi][it][0], bw[mi][it][1], h01, l01);
                    bsplit2(bw[mi][it][2], bw[mi][it][3], h23, l23);
                    uint32_t o = SWZB((uint32_t)(pn * 128 + (pkb + it * 4) * 8));
                    *(uint2*)(BH + o) = make_uint2(h01, h23);
                    *(uint2*)(BL + o) = make_uint2(l01, l23);
                }
            }
        }
        __syncthreads();

        if (ch + 1 < NCH) {
            // A(ch+1) -> alt buffer (safe: all MMA(ch-1) reads done at sync)
            uint32_t ab = uA + (uint32_t)(((ch + 1) & 1) * 16384);
            uint32_t boff = (uint32_t)((ch + 1) * 128);
            cpa16(ab + dO0, sH0 + boff, szA);
            cpa16(ab + dO1, sH1 + boff, szB);
            cpa16(ab + 8192 + dO0, sL0 + boff, szA);
            cpa16(ab + 8192 + dO1, sL1 + boff, szB);
            CPA_COMMIT();
            // B(ch+1) -> regs (hidden under MMA)
            int k0n = (ch + 1) * 64;
            #pragma unroll
            for (int mi = 0; mi < 2; mi++) {
                const float* WB = mi ? wuB : wgB;
                #pragma unroll
                for (int it = 0; it < 4; it++) {
                    const float* p = WB + (size_t)(k0n + (pkb + it * 4) * 4) * I_DIM + pn;
                    bw[mi][it][0] = p[0];
                    bw[mi][it][1] = p[I_DIM];
                    bw[mi][it][2] = p[2 * I_DIM];
                    bw[mi][it][3] = p[3 * I_DIM];
                }
            }
        }

        uint32_t uAhi = uA + (uint32_t)((ch & 1) * 16384);
        uint32_t uAlo = uAhi + 8192;
        uint32_t uBgh = uB + bsel;
        uint32_t uBgl = uBgh + 8192;
        uint32_t uBuh = uBgh + 16384;
        uint32_t uBul = uBgh + 24576;
        #pragma unroll
        for (int ks = 0; ks < 4; ks++) {
            uint32_t ah[2][4], al[2][4];
            #pragma unroll
            for (int mf = 0; mf < 2; mf++) {
                uint32_t lin = (uint32_t)((aRow + mf * 16) * 128) + (uint32_t)(ks * 32) + aKb;
                uint32_t o = SWZB(lin);
                ldm4(ah[mf], uAhi + o);
                ldm4(al[mf], uAlo + o);
            }
            uint32_t ob = SWZB((uint32_t)(bRow * 128) + (uint32_t)(ks * 32) + bKb);
            uint32_t bgh[4], bgl[4], buh[4], bul[4];
            ldm4(bgh, uBgh + ob);
            ldm4(bgl, uBgl + ob);
            ldm4(buh, uBuh + ob);
            ldm4(bul, uBul + ob);
            #pragma unroll
            for (int mf = 0; mf < 2; mf++) {
                #pragma unroll
                for (int nf = 0; nf < 2; nf++) {
                    mma16816(accg[mf][nf], ah[mf], bgh[nf * 2], bgh[nf * 2 + 1]);
                    mma16816(accg[mf][nf], ah[mf], bgl[nf * 2], bgl[nf * 2 + 1]);
                    mma16816(accg[mf][nf], al[mf], bgh[nf * 2], bgh[nf * 2 + 1]);
                    mma16816(accu[mf][nf], ah[mf], buh[nf * 2], buh[nf * 2 + 1]);
                    mma16816(accu[mf][nf], ah[mf], bul[nf * 2], bul[nf * 2 + 1]);
                    mma16816(accu[mf][nf], al[mf], buh[nf * 2], buh[nf * 2 + 1]);
                }
            }
        }
        // no trailing sync: next STS targets the other B buffer
    }

    // epilogue: a = silu(g)*u, split to bf16 hi/lo
    int lr = lane >> 2, lc = (lane & 3) * 2;
    #pragma unroll
    for (int mf = 0; mf < 2; mf++) {
        #pragma unroll
        for (int nf = 0; nf < 2; nf++) {
            int col = nt * 64 + wn * 16 + nf * 8 + lc;
            #pragma unroll
            for (int half = 0; half < 2; half++) {
                int row = wm * 32 + mf * 16 + lr + half * 8;
                if (m0 + row < ne) {
                    int rid = s_rids[row];
                    float g0 = accg[mf][nf][half * 2 + 0];
                    float g1 = accg[mf][nf][half * 2 + 1];
                    float u0 = accu[mf][nf][half * 2 + 0];
                    float u1 = accu[mf][nf][half * 2 + 1];
                    float a0 = (g0 / (1.f + expf(-g0))) * u0;
                    float a1 = (g1 / (1.f + expf(-g1))) * u1;
                    uint32_t h, l;
                    bsplit2(a0, a1, h, l);
                    size_t off = (size_t)rid * I_DIM + col;
                    *(uint32_t*)(g_ahi + off) = h;
                    *(uint32_t*)(g_alo + off) = l;
                }
            }
        }
    }
}

__global__ __launch_bounds__(256, 2) void down_kernel(const float* __restrict__ Wd)
{
    const int nt = blockIdx.x;   // 16
    const int mt = blockIdx.y;   // 4
    const int e  = blockIdx.z;   // 32
    int ne = g_cnt[e];
    int m0 = mt * 64;
    if (m0 >= ne) return;

    extern __shared__ __align__(128) char dsm[];
    // A: [0,32K) double hi/lo; B: [32K,64K): buf0 {h,l} 8KB, buf1 at +16K
    __shared__ int   s_rids[64];
    __shared__ float s_wts[64];

    int tid = threadIdx.x;
    int lane = tid & 31;
    int w = tid >> 5;
    int wm = w & 1;
    int wn = w >> 1;

    if (tid < 64) {
        int i = m0 + tid;
        if (i < ne) {
            int tk = g_tok[e * T_TOK + i];
            s_rids[tid] = tk * TOPK + g_slot[e * T_TOK + i];
            s_wts[tid]  = g_wt[e * T_TOK + i];
        } else { s_rids[tid] = -1; s_wts[tid] = 0.f; }
    }
    __syncthreads();

    uint32_t uA = smem_u32(dsm);
    uint32_t uB = uA + 32768;

    int arow0 = tid >> 3, aseg = tid & 7;
    int arow1 = arow0 + 32;
    int ridA = s_rids[arow0], ridB = s_rids[arow1];
    const char* sH0 = (const char*)g_ahi + ((size_t)(ridA < 0 ? 0 : ridA) * I_DIM) * 2 + aseg * 16;
    const char* sH1 = (const char*)g_ahi + ((size_t)(ridB < 0 ? 0 : ridB) * I_DIM) * 2 + aseg * 16;
    const char* sL0 = (const char*)g_alo + ((size_t)(ridA < 0 ? 0 : ridA) * I_DIM) * 2 + aseg * 16;
    const char* sL1 = (const char*)g_alo + ((size_t)(ridB < 0 ? 0 : ridB) * I_DIM) * 2 + aseg * 16;
    uint32_t szA = (ridA >= 0) ? 16u : 0u;
    uint32_t szB = (ridB >= 0) ? 16u : 0u;
    uint32_t dO0 = SWZB((uint32_t)(arow0 * 128 + aseg * 16));
    uint32_t dO1 = SWZB((uint32_t)(arow1 * 128 + aseg * 16));

    int aRow = wm * 32 + (lane & 15);
    uint32_t aKb = (uint32_t)((lane >> 4) * 16);
    int bRow = wn * 16 + (lane & 7) + ((lane >> 4) << 3);
    uint32_t bKb = (uint32_t)(((lane >> 3) & 1) * 16);

    float acc[2][2][4];
    #pragma unroll
    for (int a = 0; a < 2; a++)
        #pragma unroll
        for (int b = 0; b < 2; b++)
            #pragma unroll
            for (int c = 0; c < 4; c++) acc[a][b][c] = 0.f;

    const float* wdB = Wd + (size_t)e * I_DIM * H_DIM + nt * 64;
    float bw[4][4];
    int pkb = tid >> 6, pn = tid & 63;

    #pragma unroll
    for (int it = 0; it < 4; it++) {
        const float* p = wdB + (size_t)((pkb + it * 4) * 4) * H_DIM + pn;
        bw[it][0] = p[0];
        bw[it][1] = p[H_DIM];
        bw[it][2] = p[2 * H_DIM];
        bw[it][3] = p[3 * H_DIM];
    }
    cpa16(uA + dO0, sH0, szA);
    cpa16(uA + dO1, sH1, szB);
    cpa16(uA + 8192 + dO0, sL0, szA);
    cpa16(uA + 8192 + dO1, sL1, szB);
    CPA_COMMIT();

    const int NCH = I_DIM / 64;  // 8
    for (int ch = 0; ch < NCH; ch++) {
        uint32_t bsel = (uint32_t)((ch & 1) * 16384);
        CPA_WAIT0();
        {
            char* BH = dsm + 32768 + (ch & 1) * 16384;
            char* BL = BH + 8192;
            #pragma unroll
            for (int it = 0; it < 4; it++) {
                uint32_t h01, l01, h23, l23;
                bsplit2(bw[it][0], bw[it][1], h01, l01);
                bsplit2(bw[it][2], bw[it][3], h23, l23);
                uint32_t o = SWZB((uint32_t)(pn * 128 + (pkb + it * 4) * 8));
                *(uint2*)(BH + o) = make_uint2(h01, h23);
                *(uint2*)(BL + o) = make_uint2(l01, l23);
            }
        }
        __syncthreads();

        if (ch + 1 < NCH) {
            uint32_t ab = uA + (uint32_t)(((ch + 1) & 1) * 16384);
            uint32_t boff = (uint32_t)((ch + 1) * 128);
            cpa16(ab + dO0, sH0 + boff, szA);
            cpa16(ab + dO1, sH1 + boff, szB);
            cpa16(ab + 8192 + dO0, sL0 + boff, szA);
            cpa16(ab + 8192 + dO1, sL1 + boff, szB);
            CPA_COMMIT();
            int k0n = (ch + 1) * 64;
            #pragma unroll
            for (int it = 0; it < 4; it++) {
                const float* p = wdB + (size_t)(k0n + (pkb + it * 4) * 4) * H_DIM + pn;
                bw[it][0] = p[0];
                bw[it][1] = p[H_DIM];
                bw[it][2] = p[2 * H_DIM];
                bw[it][3] = p[3 * H_DIM];
            }
        }

        uint32_t uAhi = uA + (uint32_t)((ch & 1) * 16384);
        uint32_t uAlo = uAhi + 8192;
        uint32_t uBh = uB + bsel;
        uint32_t uBl = uBh + 8192;
        #pragma unroll
        for (int ks = 0; ks < 4; ks++) {
            uint32_t ah[2][4], al[2][4];
            #pragma unroll
            for (int mf = 0; mf < 2; mf++) {
                uint32_t lin = (uint32_t)((aRow + mf * 16) * 128) + (uint32_t)(ks * 32) + aKb;
                uint32_t o = SWZB(lin);
                ldm4(ah[mf], uAhi + o);
                ldm4(al[mf], uAlo + o);
            }
            uint32_t ob = SWZB((uint32_t)(bRow * 128) + (uint32_t)(ks * 32) + bKb);
            uint32_t bh[4], bl[4];
            ldm4(bh, uBh + ob);
            ldm4(bl, uBl + ob);
            #pragma unroll
            for (int mf = 0; mf < 2; mf++) {
                #pragma unroll
                for (int nf = 0; nf < 2; nf++) {
                    mma16816(acc[mf][nf], ah[mf], bh[nf * 2], bh[nf * 2 + 1]);
                    mma16816(acc[mf][nf], ah[mf], bl[nf * 2], bl[nf * 2 + 1]);
                    mma16816(acc[mf][nf], al[mf], bh[nf * 2], bh[nf * 2 + 1]);
                }
            }
        }
    }

    int lr = lane >> 2, lc = (lane & 3) * 2;
    #pragma unroll
    for (int mf = 0; mf < 2; mf++) {
        #pragma unroll
        for (int nf = 0; nf < 2; nf++) {
            int col = nt * 64 + wn * 16 + nf * 8 + lc;
            #pragma unroll
            for (int half = 0; half < 2; half++) {
                int row = wm * 32 + mf * 16 + lr + half * 8;
                if (m0 + row < ne) {
                    int rid = s_rids[row];
                    float wt = s_wts[row];
                    float2 o;
                    o.x = wt * acc[mf][nf][half * 2 + 0];
                    o.y = wt * acc[mf][nf][half * 2 + 1];
                    *(float2*)(g_ybuf + (size_t)rid * H_DIM + col) = o;
                }
            }
        }
    }
}

// ---------------- kernel 5: deterministic combine ----------------
__global__ __launch_bounds__(256) void combine_kernel(float* __restrict__ out)
{
    int idx = blockIdx.x * 256 + threadIdx.x;
    int t = idx >> 10;
    int h = idx & 1023;
    float s = 0.f;
    #pragma unroll
    for (int k = 0; k < TOPK; k++)
        s += g_ybuf[((size_t)t * TOPK + k) * H_DIM + h];
    out[idx] = s;
}

// ---------------- launch ----------------
#define GATEUP_SMEM (32768 + 65536)   // 96KB
#define DOWN_SMEM   (32768 + 32768)   // 64KB

extern "C" void kernel_launch(void* const* d_in, const int* in_sizes, int n_in,
                              void* d_out, int out_size)
{
    const float* x      = (const float*)d_in[0];
    const float* gate_w = (const float*)d_in[1];
    const float* bias   = (const float*)d_in[2];
    const float* Wg     = (const float*)d_in[3];
    const float* Wu     = (const float*)d_in[4];
    const float* Wd     = (const float*)d_in[5];
    float* out = (float*)d_out;

    cudaFuncSetAttribute(gateup_kernel, cudaFuncAttributeMaxDynamicSharedMemorySize, GATEUP_SMEM);
    cudaFuncSetAttribute(down_kernel,   cudaFuncAttributeMaxDynamicSharedMemorySize, DOWN_SMEM);

    routing_kernel<<<T_TOK, 128>>>(x, gate_w, bias);
    build_lists_kernel<<<1, 1024>>>();
    gateup_kernel<<<dim3(I_DIM / 64, 4, E_EXP), 256, GATEUP_SMEM>>>(Wg, Wu);
    down_kernel<<<dim3(H_DIM / 64, 4, E_EXP), 256, DOWN_SMEM>>>(Wd);
    combine_kernel<<<(T_TOK * H_DIM) / 256, 256>>>(out);
}

// round 7
// speedup vs baseline: 4.5649x; 1.0092x over previous
#include <cuda_runtime.h>
#include <cuda_bf16.h>
#include <math.h>
#include <stdint.h>

#define T_TOK 256
#define H_DIM 1024
#define I_DIM 512
#define E_EXP 32
#define TOPK  8
#define NGRP  8
#define GSZ   4
#define TKG   4

#define SWZB(o) ((o) ^ (((o) >> 3) & 0x70))

// ---------------- helpers ----------------
__device__ __forceinline__ uint32_t smem_u32(const void* p) {
    uint32_t a;
    asm("{ .reg .u64 t; cvta.to.shared.u64 t, %1; cvt.u32.u64 %0, t; }" : "=r"(a) : "l"(p));
    return a;
}

// split 2 fp32 -> packed bf16x2 hi + bf16x2 lo (lo = exact residual)
__device__ __forceinline__ void bsplit2(float e0, float e1, uint32_t &h, uint32_t &l) {
    asm("cvt.rn.bf16x2.f32 %0, %1, %2;" : "=r"(h) : "f"(e1), "f"(e0));
    float f0 = __uint_as_float(h << 16);
    float f1 = __uint_as_float(h & 0xFFFF0000u);
    float r0 = e0 - f0, r1 = e1 - f1;
    asm("cvt.rn.bf16x2.f32 %0, %1, %2;" : "=r"(l) : "f"(r1), "f"(r0));
}

__device__ __forceinline__ void ldm4(uint32_t r[4], uint32_t addr) {
    asm volatile("ldmatrix.sync.aligned.m8n8.x4.shared.b16 {%0,%1,%2,%3}, [%4];"
        : "=r"(r[0]), "=r"(r[1]), "=r"(r[2]), "=r"(r[3]) : "r"(addr));
}

__device__ __forceinline__ void mma16816(float d[4], const uint32_t a[4],
                                         uint32_t b0, uint32_t b1) {
    asm volatile("mma.sync.aligned.m16n8k16.row.col.f32.bf16.bf16.f32 "
        "{%0,%1,%2,%3}, {%4,%5,%6,%7}, {%8,%9}, {%0,%1,%2,%3};"
        : "+f"(d[0]), "+f"(d[1]), "+f"(d[2]), "+f"(d[3])
        : "r"(a[0]), "r"(a[1]), "r"(a[2]), "r"(a[3]), "r"(b0), "r"(b1));
}

__device__ __forceinline__ void cpa16(uint32_t dst, const void* src, uint32_t sz) {
    asm volatile("cp.async.cg.shared.global [%0], [%1], 16, %2;"
        :: "r"(dst), "l"(src), "r"(sz) : "memory");
}
#define CPA_COMMIT() asm volatile("cp.async.commit_group;" ::: "memory")
#define CPA_WAIT0()  asm volatile("cp.async.wait_group 0;" ::: "memory")

// ---------------- device scratch ----------------
__device__ int   g_topk_idx[T_TOK * TOPK];
__device__ float g_topk_w[T_TOK * TOPK];
__device__ int   g_cnt[E_EXP];
__device__ int   g_tok[E_EXP * T_TOK];
__device__ int   g_slot[E_EXP * T_TOK];
__device__ float g_wt[E_EXP * T_TOK];
__device__ uint16_t g_xhi[T_TOK * H_DIM];
__device__ uint16_t g_xlo[T_TOK * H_DIM];
__device__ uint16_t g_ahi[T_TOK * TOPK * I_DIM];
__device__ uint16_t g_alo[T_TOK * TOPK * I_DIM];
__device__ float g_ybuf[T_TOK * TOPK * H_DIM];

// ---------------- kernel 1: routing (coalesced GEMV + fused x split) ----------------
__global__ __launch_bounds__(128) void routing_kernel(
    const float* __restrict__ x, const float* __restrict__ gate_w,
    const float* __restrict__ bias)
{
    int t = blockIdx.x;
    __shared__ float xs[H_DIM];
    __shared__ float part[4][E_EXP];
    __shared__ float sc[E_EXP];
    __shared__ float sfc[E_EXP];
    int tid = threadIdx.x;
    for (int i = tid; i < H_DIM / 4; i += 128) {
        float4 v = *(const float4*)(x + (size_t)t * H_DIM + i * 4);
        *(float4*)&xs[i * 4] = v;
        uint32_t h0, l0, h1, l1;
        bsplit2(v.x, v.y, h0, l0);
        bsplit2(v.z, v.w, h1, l1);
        ((uint2*)(g_xhi + (size_t)t * H_DIM))[i] = make_uint2(h0, h1);
        ((uint2*)(g_xlo + (size_t)t * H_DIM))[i] = make_uint2(l0, l1);
    }
    __syncthreads();
    int warp = tid >> 5, lane = tid & 31;
    {
        float s = 0.f;
        const float* gw = gate_w + lane;
        int h0 = warp * (H_DIM / 4);
        #pragma unroll 4
        for (int h = h0; h < h0 + H_DIM / 4; h++)
            s += xs[h] * gw[(size_t)h * E_EXP];
        part[warp][lane] = s;
    }
    __syncthreads();
    if (tid < E_EXP) {
        float s = part[0][tid] + part[1][tid] + part[2][tid] + part[3][tid];
        float sig = 1.f / (1.f + expf(-s));
        sc[tid] = sig;
        sfc[tid] = sig + bias[tid];
    }
    __syncthreads();
    if (tid == 0) {
        float gs[NGRP];
        #pragma unroll
        for (int g = 0; g < NGRP; g++) {
            float m1 = -1e30f, m2 = -1e30f;
            #pragma unroll
            for (int j = 0; j < GSZ; j++) {
                float v = sfc[g * GSZ + j];
                if (v > m1) { m2 = m1; m1 = v; }
                else if (v > m2) { m2 = v; }
            }
            gs[g] = m1 + m2;
        }
        bool gsel[NGRP];
        #pragma unroll
        for (int g = 0; g < NGRP; g++) gsel[g] = false;
        for (int r = 0; r < TKG; r++) {
            int b = -1;
            for (int g = 0; g < NGRP; g++)
                if (!gsel[g] && (b < 0 || gs[g] > gs[b])) b = g;
            gsel[b] = true;
        }
        float masked[E_EXP];
        bool used[E_EXP];
        #pragma unroll
        for (int e = 0; e < E_EXP; e++) {
            masked[e] = gsel[e >> 2] ? sfc[e] : 0.0f;
            used[e] = false;
        }
        int idx[TOPK];
        float wsum = 0.f;
        for (int r = 0; r < TOPK; r++) {
            int b = -1;
            for (int e = 0; e < E_EXP; e++)
                if (!used[e] && (b < 0 || masked[e] > masked[b])) b = e;
            used[b] = true;
            idx[r] = b;
            wsum += sc[b];
        }
        float scale = 2.5f / (wsum + 1e-20f);
        for (int r = 0; r < TOPK; r++) {
            g_topk_idx[t * TOPK + r] = idx[r];
            g_topk_w[t * TOPK + r]   = sc[idx[r]] * scale;
        }
    }
}

// ---------------- kernel 2: warp-per-expert ballot compaction ----------------
__global__ __launch_bounds__(1024) void build_lists_kernel()
{
    int e = threadIdx.x >> 5;
    int lane = threadIdx.x & 31;
    int cnt = 0;
    for (int t0 = 0; t0 < T_TOK; t0 += 32) {
        int t = t0 + lane;
        int found = -1;
        #pragma unroll
        for (int k = 0; k < TOPK; k++)
            if (g_topk_idx[t * TOPK + k] == e) found = k;
        unsigned m = __ballot_sync(0xffffffffu, found >= 0);
        if (found >= 0) {
            int pos = cnt + __popc(m & ((1u << lane) - 1));
            g_tok [e * T_TOK + pos] = t;
            g_slot[e * T_TOK + pos] = found;
            g_wt  [e * T_TOK + pos] = g_topk_w[t * TOPK + found];
        }
        cnt += __popc(m);
    }
    if (lane == 0) g_cnt[e] = cnt;
}

// ---------------- GEMM kernels: CTA 64m x 128n, warp 32x32, K chunk 64 ----------------
// smem: A [0,32K): {A0h,A0l,A1h,A1l}@8KB; B [32K,96K): buf{Bh 16K, Bl 16K} x2

__global__ __launch_bounds__(256, 2) void gateup_kernel(
    const float* __restrict__ Wg,
    const float* __restrict__ Wu)
{
    const int nt = blockIdx.x;   // 8 : 64 I-cols (both g and u)
    const int mt = blockIdx.y;   // 4
    const int e  = blockIdx.z;   // 32
    int ne = g_cnt[e];
    int m0 = mt * 64;
    if (m0 >= ne) return;

    extern __shared__ __align__(128) char dsm[];
    __shared__ int s_rids[64];

    int tid = threadIdx.x;
    int lane = tid & 31;
    int w = tid >> 5;
    int wm = w & 1;
    int wn = w >> 1;   // 0..3

    if (tid < 64) {
        int i = m0 + tid;
        if (i < ne) {
            int tk = g_tok[e * T_TOK + i];
            s_rids[tid] = tk * TOPK + g_slot[e * T_TOK + i];
        } else s_rids[tid] = -1;
    }
    __shared__ int s_toks[64];
    if (tid < 64) {
        int i = m0 + tid;
        s_toks[tid] = (i < ne) ? g_tok[e * T_TOK + i] : -1;
    }
    __syncthreads();

    uint32_t uA = smem_u32(dsm);
    uint32_t uB = uA + 32768;

    // ---- A cp.async addressing ----
    int arow0 = tid >> 3, aseg = tid & 7;
    int arow1 = arow0 + 32;
    int tokA = s_toks[arow0], tokB = s_toks[arow1];
    const char* sH0 = (const char*)g_xhi + ((size_t)(tokA < 0 ? 0 : tokA) * H_DIM) * 2 + aseg * 16;
    const char* sH1 = (const char*)g_xhi + ((size_t)(tokB < 0 ? 0 : tokB) * H_DIM) * 2 + aseg * 16;
    const char* sL0 = (const char*)g_xlo + ((size_t)(tokA < 0 ? 0 : tokA) * H_DIM) * 2 + aseg * 16;
    const char* sL1 = (const char*)g_xlo + ((size_t)(tokB < 0 ? 0 : tokB) * H_DIM) * 2 + aseg * 16;
    uint32_t szA = (tokA >= 0) ? 16u : 0u;
    uint32_t szB = (tokB >= 0) ? 16u : 0u;
    uint32_t dO0 = SWZB((uint32_t)(arow0 * 128 + aseg * 16));
    uint32_t dO1 = SWZB((uint32_t)(arow1 * 128 + aseg * 16));

    // ldmatrix addressing
    int aRow = wm * 32 + (lane & 15);
    uint32_t aKb = (uint32_t)((lane >> 4) * 16);
    int bRow = wn * 32 + (lane & 7) + ((lane >> 4) << 3);
    uint32_t bKb = (uint32_t)(((lane >> 3) & 1) * 16);

    float acc[2][4][4];
    #pragma unroll
    for (int a = 0; a < 2; a++)
        #pragma unroll
        for (int b = 0; b < 4; b++)
            #pragma unroll
            for (int c = 0; c < 4; c++) acc[a][b][c] = 0.f;

    const float* wgB = Wg + (size_t)e * H_DIM * I_DIM + nt * 64;
    const float* wuB = Wu + (size_t)e * H_DIM * I_DIM + nt * 64;

    float bw[4][4];
    int pkb = tid >> 6, pn = tid & 63;

    // prologue: Wg(0)->regs, A(0)->buf0
    #pragma unroll
    for (int it = 0; it < 4; it++) {
        const float* p = wgB + (size_t)((pkb + it * 4) * 4) * I_DIM + pn;
        bw[it][0] = p[0]; bw[it][1] = p[I_DIM];
        bw[it][2] = p[2 * I_DIM]; bw[it][3] = p[3 * I_DIM];
    }
    cpa16(uA + dO0, sH0, szA);
    cpa16(uA + dO1, sH1, szB);
    cpa16(uA + 8192 + dO0, sL0, szA);
    cpa16(uA + 8192 + dO1, sL1, szB);
    CPA_COMMIT();

    const int NCH = H_DIM / 64;  // 16
    for (int ch = 0; ch < NCH; ch++) {
        CPA_WAIT0();
        {
            char* BH = dsm + 32768 + (ch & 1) * 32768;
            char* BL = BH + 16384;
            // pass1 (Wu half): issue direct LDGs first
            float cw[4][4];
            #pragma unroll
            for (int it = 0; it < 4; it++) {
                const float* p = wuB + (size_t)(ch * 64 + (pkb + it * 4) * 4) * I_DIM + pn;
                cw[it][0] = p[0]; cw[it][1] = p[I_DIM];
                cw[it][2] = p[2 * I_DIM]; cw[it][3] = p[3 * I_DIM];
            }
            // pass0 (Wg half) from prefetched regs
            #pragma unroll
            for (int it = 0; it < 4; it++) {
                uint32_t h01, l01, h23, l23;
                bsplit2(bw[it][0], bw[it][1], h01, l01);
                bsplit2(bw[it][2], bw[it][3], h23, l23);
                uint32_t o = SWZB((uint32_t)(pn * 128 + (pkb + it * 4) * 8));
                *(uint2*)(BH + o) = make_uint2(h01, h23);
                *(uint2*)(BL + o) = make_uint2(l01, l23);
            }
            #pragma unroll
            for (int it = 0; it < 4; it++) {
                uint32_t h01, l01, h23, l23;
                bsplit2(cw[it][0], cw[it][1], h01, l01);
                bsplit2(cw[it][2], cw[it][3], h23, l23);
                uint32_t o = SWZB((uint32_t)((64 + pn) * 128 + (pkb + it * 4) * 8));
                *(uint2*)(BH + o) = make_uint2(h01, h23);
                *(uint2*)(BL + o) = make_uint2(l01, l23);
            }
        }
        __syncthreads();

        if (ch + 1 < NCH) {
            uint32_t ab = uA + (uint32_t)(((ch + 1) & 1) * 16384);
            uint32_t boff = (uint32_t)((ch + 1) * 128);
            cpa16(ab + dO0, sH0 + boff, szA);
            cpa16(ab + dO1, sH1 + boff, szB);
            cpa16(ab + 8192 + dO0, sL0 + boff, szA);
            cpa16(ab + 8192 + dO1, sL1 + boff, szB);
            CPA_COMMIT();
            int k0n = (ch + 1) * 64;
            #pragma unroll
            for (int it = 0; it < 4; it++) {
                const float* p = wgB + (size_t)(k0n + (pkb + it * 4) * 4) * I_DIM + pn;
                bw[it][0] = p[0]; bw[it][1] = p[I_DIM];
                bw[it][2] = p[2 * I_DIM]; bw[it][3] = p[3 * I_DIM];
            }
        }

        uint32_t uAhi = uA + (uint32_t)((ch & 1) * 16384);
        uint32_t uAlo = uAhi + 8192;
        uint32_t uBh = uB + (uint32_t)((ch & 1) * 32768);
        uint32_t uBl = uBh + 16384;
        #pragma unroll
        for (int ks = 0; ks < 4; ks++) {
            uint32_t ah[2][4], al[2][4];
            #pragma unroll
            for (int mf = 0; mf < 2; mf++) {
                uint32_t o = SWZB((uint32_t)((aRow + mf * 16) * 128) + (uint32_t)(ks * 32) + aKb);
                ldm4(ah[mf], uAhi + o);
                ldm4(al[mf], uAlo + o);
            }
            uint32_t ob1 = SWZB((uint32_t)(bRow * 128) + (uint32_t)(ks * 32) + bKb);
            uint32_t ob2 = SWZB((uint32_t)((bRow + 16) * 128) + (uint32_t)(ks * 32) + bKb);
            uint32_t bh[8], bl[8];
            ldm4(bh, uBh + ob1);
            ldm4(bh + 4, uBh + ob2);
            ldm4(bl, uBl + ob1);
            ldm4(bl + 4, uBl + ob2);
            #pragma unroll
            for (int mf = 0; mf < 2; mf++) {
                #pragma unroll
                for (int nf = 0; nf < 4; nf++) {
                    mma16816(acc[mf][nf], ah[mf], bh[nf * 2], bh[nf * 2 + 1]);
                    mma16816(acc[mf][nf], ah[mf], bl[nf * 2], bl[nf * 2 + 1]);
                    mma16816(acc[mf][nf], al[mf], bh[nf * 2], bh[nf * 2 + 1]);
                }
            }
        }
    }

    // ---- epilogue: stage accs to smem, then a = silu(g)*u ----
    __syncthreads();                       // all A/B reads done
    float* stg = (float*)dsm;              // [64][128] fp32 = 32KB
    int lr = lane >> 2, lc = (lane & 3) * 2;
    #pragma unroll
    for (int mf = 0; mf < 2; mf++) {
        #pragma unroll
        for (int nf = 0; nf < 4; nf++) {
            int col = wn * 32 + nf * 8 + lc;   // 0..63 = g, 64..127 = u
            #pragma unroll
            for (int half = 0; half < 2; half++) {
                int row = wm * 32 + mf * 16 + lr + half * 8;
                *(float2*)&stg[row * 128 + col] =
                    make_float2(acc[mf][nf][half * 2], acc[mf][nf][half * 2 + 1]);
            }
        }
    }
    __syncthreads();
    #pragma unroll
    for (int p = 0; p < 8; p++) {
        int idx = tid + p * 256;       // 2048 = 64 rows x 32 col-pairs
        int row = idx >> 5;
        int cp = idx & 31;
        int rid = s_rids[row];
        if (rid >= 0) {
            float2 g = *(float2*)&stg[row * 128 + cp * 2];
            float2 u = *(float2*)&stg[row * 128 + 64 + cp * 2];
            float a0 = (g.x / (1.f + expf(-g.x))) * u.x;
            float a1 = (g.y / (1.f + expf(-g.y))) * u.y;
            uint32_t h, l;
            bsplit2(a0, a1, h, l);
            size_t off = (size_t)rid * I_DIM + nt * 64 + cp * 2;
            *(uint32_t*)(g_ahi + off) = h;
            *(uint32_t*)(g_alo + off) = l;
        }
    }
}

__global__ __launch_bounds__(256, 2) void down_kernel(const float* __restrict__ Wd)
{
    const int nt = blockIdx.x;   // 8 : 128 H-cols
    const int mt = blockIdx.y;   // 4
    const int e  = blockIdx.z;   // 32
    int ne = g_cnt[e];
    int m0 = mt * 64;
    if (m0 >= ne) return;

    extern __shared__ __align__(128) char dsm[];
    __shared__ int   s_rids[64];
    __shared__ float s_wts[64];

    int tid = threadIdx.x;
    int lane = tid & 31;
    int w = tid >> 5;
    int wm = w & 1;
    int wn = w >> 1;

    if (tid < 64) {
        int i = m0 + tid;
        if (i < ne) {
            int tk = g_tok[e * T_TOK + i];
            s_rids[tid] = tk * TOPK + g_slot[e * T_TOK + i];
            s_wts[tid]  = g_wt[e * T_TOK + i];
        } else { s_rids[tid] = -1; s_wts[tid] = 0.f; }
    }
    __syncthreads();

    uint32_t uA = smem_u32(dsm);
    uint32_t uB = uA + 32768;

    int arow0 = tid >> 3, aseg = tid & 7;
    int arow1 = arow0 + 32;
    int ridA = s_rids[arow0], ridB = s_rids[arow1];
    const char* sH0 = (const char*)g_ahi + ((size_t)(ridA < 0 ? 0 : ridA) * I_DIM) * 2 + aseg * 16;
    const char* sH1 = (const char*)g_ahi + ((size_t)(ridB < 0 ? 0 : ridB) * I_DIM) * 2 + aseg * 16;
    const char* sL0 = (const char*)g_alo + ((size_t)(ridA < 0 ? 0 : ridA) * I_DIM) * 2 + aseg * 16;
    const char* sL1 = (const char*)g_alo + ((size_t)(ridB < 0 ? 0 : ridB) * I_DIM) * 2 + aseg * 16;
    uint32_t szA = (ridA >= 0) ? 16u : 0u;
    uint32_t szB = (ridB >= 0) ? 16u : 0u;
    uint32_t dO0 = SWZB((uint32_t)(arow0 * 128 + aseg * 16));
    uint32_t dO1 = SWZB((uint32_t)(arow1 * 128 + aseg * 16));

    int aRow = wm * 32 + (lane & 15);
    uint32_t aKb = (uint32_t)((lane >> 4) * 16);
    int bRow = wn * 32 + (lane & 7) + ((lane >> 4) << 3);
    uint32_t bKb = (uint32_t)(((lane >> 3) & 1) * 16);

    float acc[2][4][4];
    #pragma unroll
    for (int a = 0; a < 2; a++)
        #pragma unroll
        for (int b = 0; b < 4; b++)
            #pragma unroll
            for (int c = 0; c < 4; c++) acc[a][b][c] = 0.f;

    const float* wdB = Wd + (size_t)e * I_DIM * H_DIM + nt * 128;
    float bw[4][4];
    int pkb = tid >> 6, pn = tid & 63;

    #pragma unroll
    for (int it = 0; it < 4; it++) {
        const float* p = wdB + (size_t)((pkb + it * 4) * 4) * H_DIM + pn;
        bw[it][0] = p[0]; bw[it][1] = p[H_DIM];
        bw[it][2] = p[2 * H_DIM]; bw[it][3] = p[3 * H_DIM];
    }
    cpa16(uA + dO0, sH0, szA);
    cpa16(uA + dO1, sH1, szB);
    cpa16(uA + 8192 + dO0, sL0, szA);
    cpa16(uA + 8192 + dO1, sL1, szB);
    CPA_COMMIT();

    const int NCH = I_DIM / 64;  // 8
    for (int ch = 0; ch < NCH; ch++) {
        CPA_WAIT0();
        {
            char* BH = dsm + 32768 + (ch & 1) * 32768;
            char* BL = BH + 16384;
            float cw[4][4];
            #pragma unroll
            for (int it = 0; it < 4; it++) {
                const float* p = wdB + (size_t)(ch * 64 + (pkb + it * 4) * 4) * H_DIM + 64 + pn;
                cw[it][0] = p[0]; cw[it][1] = p[H_DIM];
                cw[it][2] = p[2 * H_DIM]; cw[it][3] = p[3 * H_DIM];
            }
            #pragma unroll
            for (int it = 0; it < 4; it++) {
                uint32_t h01, l01, h23, l23;
                bsplit2(bw[it][0], bw[it][1], h01, l01);
                bsplit2(bw[it][2], bw[it][3], h23, l23);
                uint32_t o = SWZB((uint32_t)(pn * 128 + (pkb + it * 4) * 8));
                *(uint2*)(BH + o) = make_uint2(h01, h23);
                *(uint2*)(BL + o) = make_uint2(l01, l23);
            }
            #pragma unroll
            for (int it = 0; it < 4; it++) {
                uint32_t h01, l01, h23, l23;
                bsplit2(cw[it][0], cw[it][1], h01, l01);
                bsplit2(cw[it][2], cw[it][3], h23, l23);
                uint32_t o = SWZB((uint32_t)((64 + pn) * 128 + (pkb + it * 4) * 8));
                *(uint2*)(BH + o) = make_uint2(h01, h23);
                *(uint2*)(BL + o) = make_uint2(l01, l23);
            }
        }
        __syncthreads();

        if (ch + 1 < NCH) {
            uint32_t ab = uA + (uint32_t)(((ch + 1) & 1) * 16384);
            uint32_t boff = (uint32_t)((ch + 1) * 128);
            cpa16(ab + dO0, sH0 + boff, szA);
            cpa16(ab + dO1, sH1 + boff, szB);
            cpa16(ab + 8192 + dO0, sL0 + boff, szA);
            cpa16(ab + 8192 + dO1, sL1 + boff, szB);
            CPA_COMMIT();
            int k0n = (ch + 1) * 64;
            #pragma unroll
            for (int it = 0; it < 4; it++) {
                const float* p = wdB + (size_t)(k0n + (pkb + it * 4) * 4) * H_DIM + pn;
                bw[it][0] = p[0]; bw[it][1] = p[H_DIM];
                bw[it][2] = p[2 * H_DIM]; bw[it][3] = p[3 * H_DIM];
            }
        }

        uint32_t uAhi = uA + (uint32_t)((ch & 1) * 16384);
        uint32_t uAlo = uAhi + 8192;
        uint32_t uBh = uB + (uint32_t)((ch & 1) * 32768);
        uint32_t uBl = uBh + 16384;
        #pragma unroll
        for (int ks = 0; ks < 4; ks++) {
            uint32_t ah[2][4], al[2][4];
            #pragma unroll
            for (int mf = 0; mf < 2; mf++) {
                uint32_t o = SWZB((uint32_t)((aRow + mf * 16) * 128) + (uint32_t)(ks * 32) + aKb);
                ldm4(ah[mf], uAhi + o);
                ldm4(al[mf], uAlo + o);
            }
            uint32_t ob1 = SWZB((uint32_t)(bRow * 128) + (uint32_t)(ks * 32) + bKb);
            uint32_t ob2 = SWZB((uint32_t)((bRow + 16) * 128) + (uint32_t)(ks * 32) + bKb);
            uint32_t bh[8], bl[8];
            ldm4(bh, uBh + ob1);
            ldm4(bh + 4, uBh + ob2);
            ldm4(bl, uBl + ob1);
            ldm4(bl + 4, uBl + ob2);
            #pragma unroll
            for (int mf = 0; mf < 2; mf++) {
                #pragma unroll
                for (int nf = 0; nf < 4; nf++) {
                    mma16816(acc[mf][nf], ah[mf], bh[nf * 2], bh[nf * 2 + 1]);
                    mma16816(acc[mf][nf], ah[mf], bl[nf * 2], bl[nf * 2 + 1]);
                    mma16816(acc[mf][nf], al[mf], bh[nf * 2], bh[nf * 2 + 1]);
                }
            }
        }
    }

    int lr = lane >> 2, lc = (lane & 3) * 2;
    #pragma unroll
    for (int mf = 0; mf < 2; mf++) {
        #pragma unroll
        for (int nf = 0; nf < 4; nf++) {
            int col = nt * 128 + wn * 32 + nf * 8 + lc;
            #pragma unroll
            for (int half = 0; half < 2; half++) {
                int row = wm * 32 + mf * 16 + lr + half * 8;
                if (m0 + row < ne) {
                    int rid = s_rids[row];
                    float wt = s_wts[row];
                    float2 o;
                    o.x = wt * acc[mf][nf][half * 2 + 0];
                    o.y = wt * acc[mf][nf][half * 2 + 1];
                    *(float2*)(g_ybuf + (size_t)rid * H_DIM + col) = o;
                }
            }
        }
    }
}

// ---------------- kernel 5: deterministic combine ----------------
__global__ __launch_bounds__(256) void combine_kernel(float* __restrict__ out)
{
    int idx = blockIdx.x * 256 + threadIdx.x;
    int t = idx >> 10;
    int h = idx & 1023;
    float s = 0.f;
    #pragma unroll
    for (int k = 0; k < TOPK; k++)
        s += g_ybuf[((size_t)t * TOPK + k) * H_DIM + h];
    out[idx] = s;
}

// ---------------- launch ----------------
#define GEMM_SMEM (32768 + 65536)   // 96KB

extern "C" void kernel_launch(void* const* d_in, const int* in_sizes, int n_in,
                              void* d_out, int out_size)
{
    const float* x      = (const float*)d_in[0];
    const float* gate_w = (const float*)d_in[1];
    const float* bias   = (const float*)d_in[2];
    const float* Wg     = (const float*)d_in[3];
    const float* Wu     = (const float*)d_in[4];
    const float* Wd     = (const float*)d_in[5];
    float* out = (float*)d_out;

    cudaFuncSetAttribute(gateup_kernel, cudaFuncAttributeMaxDynamicSharedMemorySize, GEMM_SMEM);
    cudaFuncSetAttribute(down_kernel,   cudaFuncAttributeMaxDynamicSharedMemorySize, GEMM_SMEM);

    routing_kernel<<<T_TOK, 128>>>(x, gate_w, bias);
    build_lists_kernel<<<1, 1024>>>();
    gateup_kernel<<<dim3(I_DIM / 64, 4, E_EXP), 256, GEMM_SMEM>>>(Wg, Wu);
    down_kernel<<<dim3(H_DIM / 128, 4, E_EXP), 256, GEMM_SMEM>>>(Wd);
    combine_kernel<<<(T_TOK * H_DIM) / 256, 256>>>(out);
}

// round 8
// speedup vs baseline: 4.7365x; 1.0376x over previous
#include <cuda_runtime.h>
#include <cuda_bf16.h>
#include <math.h>
#include <stdint.h>

#define T_TOK 256
#define H_DIM 1024
#define I_DIM 512
#define E_EXP 32
#define TOPK  8
#define NGRP  8
#define GSZ   4
#define TKG   4

#define SWZB(o) ((o) ^ (((o) >> 3) & 0x70))

// ---------------- helpers ----------------
__device__ __forceinline__ uint32_t smem_u32(const void* p) {
    uint32_t a;
    asm("{ .reg .u64 t; cvta.to.shared.u64 t, %1; cvt.u32.u64 %0, t; }" : "=r"(a) : "l"(p));
    return a;
}

// split 2 fp32 -> packed bf16x2 hi + bf16x2 lo (lo = exact residual)
__device__ __forceinline__ void bsplit2(float e0, float e1, uint32_t &h, uint32_t &l) {
    asm("cvt.rn.bf16x2.f32 %0, %1, %2;" : "=r"(h) : "f"(e1), "f"(e0));
    float f0 = __uint_as_float(h << 16);
    float f1 = __uint_as_float(h & 0xFFFF0000u);
    float r0 = e0 - f0, r1 = e1 - f1;
    asm("cvt.rn.bf16x2.f32 %0, %1, %2;" : "=r"(l) : "f"(r1), "f"(r0));
}

__device__ __forceinline__ void ldm4(uint32_t r[4], uint32_t addr) {
    asm volatile("ldmatrix.sync.aligned.m8n8.x4.shared.b16 {%0,%1,%2,%3}, [%4];"
        : "=r"(r[0]), "=r"(r[1]), "=r"(r[2]), "=r"(r[3]) : "r"(addr));
}

__device__ __forceinline__ void mma16816(float d[4], const uint32_t a[4],
                                         uint32_t b0, uint32_t b1) {
    asm volatile("mma.sync.aligned.m16n8k16.row.col.f32.bf16.bf16.f32 "
        "{%0,%1,%2,%3}, {%4,%5,%6,%7}, {%8,%9}, {%0,%1,%2,%3};"
        : "+f"(d[0]), "+f"(d[1]), "+f"(d[2]), "+f"(d[3])
        : "r"(a[0]), "r"(a[1]), "r"(a[2]), "r"(a[3]), "r"(b0), "r"(b1));
}

__device__ __forceinline__ void cpa16(uint32_t dst, const void* src, uint32_t sz) {
    asm volatile("cp.async.cg.shared.global [%0], [%1], 16, %2;"
        :: "r"(dst), "l"(src), "r"(sz) : "memory");
}
#define CPA_COMMIT() asm volatile("cp.async.commit_group;" ::: "memory")
#define CPA_WAIT0()  asm volatile("cp.async.wait_group 0;" ::: "memory")

// ---------------- device scratch ----------------
__device__ int   g_topk_idx[T_TOK * TOPK];
__device__ float g_topk_w[T_TOK * TOPK];
__device__ int   g_cnt[E_EXP];
__device__ int   g_tok[E_EXP * T_TOK];
__device__ int   g_slot[E_EXP * T_TOK];
__device__ float g_wt[E_EXP * T_TOK];
__device__ uint16_t g_xhi[T_TOK * H_DIM];
__device__ uint16_t g_xlo[T_TOK * H_DIM];
__device__ uint16_t g_ahi[T_TOK * TOPK * I_DIM];
__device__ uint16_t g_alo[T_TOK * TOPK * I_DIM];
__device__ float g_ybuf[T_TOK * TOPK * H_DIM];

// work queue
__device__ int g_pairs[E_EXP * 4];   // (e<<2)|mt
__device__ int g_npair;
__device__ int g_ctr;
__device__ int g_rdy[E_EXP * 4];     // per-pair gateup completion count (target 8)

// ---------------- kernel 1: routing (coalesced GEMV + fused x split) ----------------
__global__ __launch_bounds__(128) void routing_kernel(
    const float* __restrict__ x, const float* __restrict__ gate_w,
    const float* __restrict__ bias)
{
    int t = blockIdx.x;
    __shared__ float xs[H_DIM];
    __shared__ float part[4][E_EXP];
    __shared__ float sc[E_EXP];
    __shared__ float sfc[E_EXP];
    int tid = threadIdx.x;
    for (int i = tid; i < H_DIM / 4; i += 128) {
        float4 v = *(const float4*)(x + (size_t)t * H_DIM + i * 4);
        *(float4*)&xs[i * 4] = v;
        uint32_t h0, l0, h1, l1;
        bsplit2(v.x, v.y, h0, l0);
        bsplit2(v.z, v.w, h1, l1);
        ((uint2*)(g_xhi + (size_t)t * H_DIM))[i] = make_uint2(h0, h1);
        ((uint2*)(g_xlo + (size_t)t * H_DIM))[i] = make_uint2(l0, l1);
    }
    __syncthreads();
    int warp = tid >> 5, lane = tid & 31;
    {
        float s = 0.f;
        const float* gw = gate_w + lane;
        int h0 = warp * (H_DIM / 4);
        #pragma unroll 4
        for (int h = h0; h < h0 + H_DIM / 4; h++)
            s += xs[h] * gw[(size_t)h * E_EXP];
        part[warp][lane] = s;
    }
    __syncthreads();
    if (tid < E_EXP) {
        float s = part[0][tid] + part[1][tid] + part[2][tid] + part[3][tid];
        float sig = 1.f / (1.f + expf(-s));
        sc[tid] = sig;
        sfc[tid] = sig + bias[tid];
    }
    __syncthreads();
    if (tid == 0) {
        float gs[NGRP];
        #pragma unroll
        for (int g = 0; g < NGRP; g++) {
            float m1 = -1e30f, m2 = -1e30f;
            #pragma unroll
            for (int j = 0; j < GSZ; j++) {
                float v = sfc[g * GSZ + j];
                if (v > m1) { m2 = m1; m1 = v; }
                else if (v > m2) { m2 = v; }
            }
            gs[g] = m1 + m2;
        }
        bool gsel[NGRP];
        #pragma unroll
        for (int g = 0; g < NGRP; g++) gsel[g] = false;
        for (int r = 0; r < TKG; r++) {
            int b = -1;
            for (int g = 0; g < NGRP; g++)
                if (!gsel[g] && (b < 0 || gs[g] > gs[b])) b = g;
            gsel[b] = true;
        }
        float masked[E_EXP];
        bool used[E_EXP];
        #pragma unroll
        for (int e = 0; e < E_EXP; e++) {
            masked[e] = gsel[e >> 2] ? sfc[e] : 0.0f;
            used[e] = false;
        }
        int idx[TOPK];
        float wsum = 0.f;
        for (int r = 0; r < TOPK; r++) {
            int b = -1;
            for (int e = 0; e < E_EXP; e++)
                if (!used[e] && (b < 0 || masked[e] > masked[b])) b = e;
            used[b] = true;
            idx[r] = b;
            wsum += sc[b];
        }
        float scale = 2.5f / (wsum + 1e-20f);
        for (int r = 0; r < TOPK; r++) {
            g_topk_idx[t * TOPK + r] = idx[r];
            g_topk_w[t * TOPK + r]   = sc[idx[r]] * scale;
        }
    }
}

// ---------------- kernel 2: compaction + work-queue setup ----------------
__global__ __launch_bounds__(1024) void build_lists_kernel()
{
    int e = threadIdx.x >> 5;
    int lane = threadIdx.x & 31;
    int cnt = 0;
    for (int t0 = 0; t0 < T_TOK; t0 += 32) {
        int t = t0 + lane;
        int found = -1;
        #pragma unroll
        for (int k = 0; k < TOPK; k++)
            if (g_topk_idx[t * TOPK + k] == e) found = k;
        unsigned m = __ballot_sync(0xffffffffu, found >= 0);
        if (found >= 0) {
            int pos = cnt + __popc(m & ((1u << lane) - 1));
            g_tok [e * T_TOK + pos] = t;
            g_slot[e * T_TOK + pos] = found;
            g_wt  [e * T_TOK + pos] = g_topk_w[t * TOPK + found];
        }
        cnt += __popc(m);
    }
    if (lane == 0) g_cnt[e] = cnt;
    if (threadIdx.x < E_EXP * 4) g_rdy[threadIdx.x] = 0;
    __syncthreads();
    if (threadIdx.x == 0) {
        int n = 0;
        for (int ee = 0; ee < E_EXP; ee++) {
            int c = g_cnt[ee];
            for (int mt = 0; mt * 64 < c; mt++) g_pairs[n++] = (ee << 2) | mt;
        }
        g_npair = n;
        g_ctr = 0;
    }
}

// ---------------- fused persistent GEMM kernel ----------------
// Work queue: items [0, npair*8) = gateup tiles (pair, nt in I/64),
// items [npair*8, npair*16) = down tiles (pair, nt in H/128).
// Down tiles wait on g_rdy[pair] == 8.
// smem: A [0,32K): {A0h,A0l,A1h,A1l}@8KB; B [32K,96K): {Bh 16K, Bl 16K} x2

__global__ __launch_bounds__(256, 2) void moe_gemm_kernel(
    const float* __restrict__ Wg,
    const float* __restrict__ Wu,
    const float* __restrict__ Wd)
{
    extern __shared__ __align__(128) char dsm[];
    __shared__ int   s_widx;
    __shared__ int   s_toks[64];
    __shared__ int   s_rids[64];
    __shared__ float s_wts[64];

    int tid = threadIdx.x;
    int lane = tid & 31;
    int w = tid >> 5;
    int wm = w & 1;
    int wn = w >> 1;   // 0..3

    uint32_t uA = smem_u32(dsm);
    uint32_t uB = uA + 32768;

    int arow0 = tid >> 3, aseg = tid & 7;
    int arow1 = arow0 + 32;
    uint32_t dO0 = SWZB((uint32_t)(arow0 * 128 + aseg * 16));
    uint32_t dO1 = SWZB((uint32_t)(arow1 * 128 + aseg * 16));

    int aRow = wm * 32 + (lane & 15);
    uint32_t aKb = (uint32_t)((lane >> 4) * 16);
    int bRow = wn * 32 + (lane & 7) + ((lane >> 4) << 3);
    uint32_t bKb = (uint32_t)(((lane >> 3) & 1) * 16);

    int pkb = tid >> 6, pn = tid & 63;
    int lr = lane >> 2, lc = (lane & 3) * 2;

    for (;;) {
        __syncthreads();
        if (tid == 0) s_widx = atomicAdd(&g_ctr, 1);
        __syncthreads();
        int widx = s_widx;
        int npair = g_npair;
        if (widx >= npair * 16) return;

        if (widx < npair * 8) {
            // ================= GATEUP TILE =================
            int pidx = widx >> 3;
            int nt = widx & 7;
            int pr = g_pairs[pidx];
            int e = pr >> 2, mt = pr & 3;
            int ne = g_cnt[e];
            int m0 = mt * 64;

            if (tid < 64) {
                int i = m0 + tid;
                if (i < ne) {
                    int tk = g_tok[e * T_TOK + i];
                    s_toks[tid] = tk;
                    s_rids[tid] = tk * TOPK + g_slot[e * T_TOK + i];
                } else { s_toks[tid] = -1; s_rids[tid] = -1; }
            }
            __syncthreads();

            int tokA = s_toks[arow0], tokB = s_toks[arow1];
            const char* sH0 = (const char*)g_xhi + ((size_t)(tokA < 0 ? 0 : tokA) * H_DIM) * 2 + aseg * 16;
            const char* sH1 = (const char*)g_xhi + ((size_t)(tokB < 0 ? 0 : tokB) * H_DIM) * 2 + aseg * 16;
            const char* sL0 = (const char*)g_xlo + ((size_t)(tokA < 0 ? 0 : tokA) * H_DIM) * 2 + aseg * 16;
            const char* sL1 = (const char*)g_xlo + ((size_t)(tokB < 0 ? 0 : tokB) * H_DIM) * 2 + aseg * 16;
            uint32_t szA = (tokA >= 0) ? 16u : 0u;
            uint32_t szB = (tokB >= 0) ? 16u : 0u;

            float acc[2][4][4];
            #pragma unroll
            for (int a = 0; a < 2; a++)
                #pragma unroll
                for (int b = 0; b < 4; b++)
                    #pragma unroll
                    for (int c = 0; c < 4; c++) acc[a][b][c] = 0.f;

            const float* wgB = Wg + (size_t)e * H_DIM * I_DIM + nt * 64;
            const float* wuB = Wu + (size_t)e * H_DIM * I_DIM + nt * 64;

            float bw[4][4];
            #pragma unroll
            for (int it = 0; it < 4; it++) {
                const float* p = wgB + (size_t)((pkb + it * 4) * 4) * I_DIM + pn;
                bw[it][0] = p[0]; bw[it][1] = p[I_DIM];
                bw[it][2] = p[2 * I_DIM]; bw[it][3] = p[3 * I_DIM];
            }
            cpa16(uA + dO0, sH0, szA);
            cpa16(uA + dO1, sH1, szB);
            cpa16(uA + 8192 + dO0, sL0, szA);
            cpa16(uA + 8192 + dO1, sL1, szB);
            CPA_COMMIT();

            const int NCH = H_DIM / 64;  // 16
            for (int ch = 0; ch < NCH; ch++) {
                CPA_WAIT0();
                {
                    char* BH = dsm + 32768 + (ch & 1) * 32768;
                    char* BL = BH + 16384;
                    float cw[4][4];
                    #pragma unroll
                    for (int it = 0; it < 4; it++) {
                        const float* p = wuB + (size_t)(ch * 64 + (pkb + it * 4) * 4) * I_DIM + pn;
                        cw[it][0] = p[0]; cw[it][1] = p[I_DIM];
                        cw[it][2] = p[2 * I_DIM]; cw[it][3] = p[3 * I_DIM];
                    }
                    #pragma unroll
                    for (int it = 0; it < 4; it++) {
                        uint32_t h01, l01, h23, l23;
                        bsplit2(bw[it][0], bw[it][1], h01, l01);
                        bsplit2(bw[it][2], bw[it][3], h23, l23);
                        uint32_t o = SWZB((uint32_t)(pn * 128 + (pkb + it * 4) * 8));
                        *(uint2*)(BH + o) = make_uint2(h01, h23);
                        *(uint2*)(BL + o) = make_uint2(l01, l23);
                    }
                    #pragma unroll
                    for (int it = 0; it < 4; it++) {
                        uint32_t h01, l01, h23, l23;
                        bsplit2(cw[it][0], cw[it][1], h01, l01);
                        bsplit2(cw[it][2], cw[it][3], h23, l23);
                        uint32_t o = SWZB((uint32_t)((64 + pn) * 128 + (pkb + it * 4) * 8));
                        *(uint2*)(BH + o) = make_uint2(h01, h23);
                        *(uint2*)(BL + o) = make_uint2(l01, l23);
                    }
                }
                __syncthreads();

                if (ch + 1 < NCH) {
                    uint32_t ab = uA + (uint32_t)(((ch + 1) & 1) * 16384);
                    uint32_t boff = (uint32_t)((ch + 1) * 128);
                    cpa16(ab + dO0, sH0 + boff, szA);
                    cpa16(ab + dO1, sH1 + boff, szB);
                    cpa16(ab + 8192 + dO0, sL0 + boff, szA);
                    cpa16(ab + 8192 + dO1, sL1 + boff, szB);
                    CPA_COMMIT();
                    int k0n = (ch + 1) * 64;
                    #pragma unroll
                    for (int it = 0; it < 4; it++) {
                        const float* p = wgB + (size_t)(k0n + (pkb + it * 4) * 4) * I_DIM + pn;
                        bw[it][0] = p[0]; bw[it][1] = p[I_DIM];
                        bw[it][2] = p[2 * I_DIM]; bw[it][3] = p[3 * I_DIM];
                    }
                }

                uint32_t uAhi = uA + (uint32_t)((ch & 1) * 16384);
                uint32_t uAlo = uAhi + 8192;
                uint32_t uBh = uB + (uint32_t)((ch & 1) * 32768);
                uint32_t uBl = uBh + 16384;
                #pragma unroll
                for (int ks = 0; ks < 4; ks++) {
                    uint32_t ah[2][4], al[2][4];
                    #pragma unroll
                    for (int mf = 0; mf < 2; mf++) {
                        uint32_t o = SWZB((uint32_t)((aRow + mf * 16) * 128) + (uint32_t)(ks * 32) + aKb);
                        ldm4(ah[mf], uAhi + o);
                        ldm4(al[mf], uAlo + o);
                    }
                    uint32_t ob1 = SWZB((uint32_t)(bRow * 128) + (uint32_t)(ks * 32) + bKb);
                    uint32_t ob2 = SWZB((uint32_t)((bRow + 16) * 128) + (uint32_t)(ks * 32) + bKb);
                    uint32_t bh[8], bl[8];
                    ldm4(bh, uBh + ob1);
                    ldm4(bh + 4, uBh + ob2);
                    ldm4(bl, uBl + ob1);
                    ldm4(bl + 4, uBl + ob2);
                    #pragma unroll
                    for (int mf = 0; mf < 2; mf++) {
                        #pragma unroll
                        for (int nf = 0; nf < 4; nf++) {
                            mma16816(acc[mf][nf], ah[mf], bh[nf * 2], bh[nf * 2 + 1]);
                            mma16816(acc[mf][nf], ah[mf], bl[nf * 2], bl[nf * 2 + 1]);
                            mma16816(acc[mf][nf], al[mf], bh[nf * 2], bh[nf * 2 + 1]);
                        }
                    }
                }
            }

            // epilogue: stage to smem, a = silu(g)*u, write bf16 hi/lo
            __syncthreads();
            float* stg = (float*)dsm;
            #pragma unroll
            for (int mf = 0; mf < 2; mf++) {
                #pragma unroll
                for (int nf = 0; nf < 4; nf++) {
                    int col = wn * 32 + nf * 8 + lc;
                    #pragma unroll
                    for (int half = 0; half < 2; half++) {
                        int row = wm * 32 + mf * 16 + lr + half * 8;
                        *(float2*)&stg[row * 128 + col] =
                            make_float2(acc[mf][nf][half * 2], acc[mf][nf][half * 2 + 1]);
                    }
                }
            }
            __syncthreads();
            #pragma unroll
            for (int p = 0; p < 8; p++) {
                int idx2 = tid + p * 256;
                int row = idx2 >> 5;
                int cp = idx2 & 31;
                int rid = s_rids[row];
                if (rid >= 0) {
                    float2 g = *(float2*)&stg[row * 128 + cp * 2];
                    float2 u = *(float2*)&stg[row * 128 + 64 + cp * 2];
                    float a0 = (g.x / (1.f + expf(-g.x))) * u.x;
                    float a1 = (g.y / (1.f + expf(-g.y))) * u.y;
                    uint32_t h, l;
                    bsplit2(a0, a1, h, l);
                    size_t off = (size_t)rid * I_DIM + nt * 64 + cp * 2;
                    *(uint32_t*)(g_ahi + off) = h;
                    *(uint32_t*)(g_alo + off) = l;
                }
            }
            // publish completion (all threads fence, then one arrives)
            __threadfence();
            __syncthreads();
            if (tid == 0) atomicAdd(&g_rdy[pidx], 1);
        } else {
            // ================= DOWN TILE =================
            int w2 = widx - npair * 8;
            int pidx = w2 >> 3;
            int nt = w2 & 7;
            int pr = g_pairs[pidx];
            int e = pr >> 2, mt = pr & 3;
            int ne = g_cnt[e];
            int m0 = mt * 64;

            // wait for all 8 gateup tiles of this pair
            if (tid == 0) {
                while (atomicAdd(&g_rdy[pidx], 0) < 8) { }
            }
            __syncthreads();

            if (tid < 64) {
                int i = m0 + tid;
                if (i < ne) {
                    int tk = g_tok[e * T_TOK + i];
                    s_rids[tid] = tk * TOPK + g_slot[e * T_TOK + i];
                    s_wts[tid]  = g_wt[e * T_TOK + i];
                } else { s_rids[tid] = -1; s_wts[tid] = 0.f; }
            }
            __syncthreads();

            int ridA = s_rids[arow0], ridB = s_rids[arow1];
            const char* sH0 = (const char*)g_ahi + ((size_t)(ridA < 0 ? 0 : ridA) * I_DIM) * 2 + aseg * 16;
            const char* sH1 = (const char*)g_ahi + ((size_t)(ridB < 0 ? 0 : ridB) * I_DIM) * 2 + aseg * 16;
            const char* sL0 = (const char*)g_alo + ((size_t)(ridA < 0 ? 0 : ridA) * I_DIM) * 2 + aseg * 16;
            const char* sL1 = (const char*)g_alo + ((size_t)(ridB < 0 ? 0 : ridB) * I_DIM) * 2 + aseg * 16;
            uint32_t szA = (ridA >= 0) ? 16u : 0u;
            uint32_t szB = (ridB >= 0) ? 16u : 0u;

            float acc[2][4][4];
            #pragma unroll
            for (int a = 0; a < 2; a++)
                #pragma unroll
                for (int b = 0; b < 4; b++)
                    #pragma unroll
                    for (int c = 0; c < 4; c++) acc[a][b][c] = 0.f;

            const float* wdB = Wd + (size_t)e * I_DIM * H_DIM + nt * 128;
            float bw[4][4];
            #pragma unroll
            for (int it = 0; it < 4; it++) {
                const float* p = wdB + (size_t)((pkb + it * 4) * 4) * H_DIM + pn;
                bw[it][0] = p[0]; bw[it][1] = p[H_DIM];
                bw[it][2] = p[2 * H_DIM]; bw[it][3] = p[3 * H_DIM];
            }
            cpa16(uA + dO0, sH0, szA);
            cpa16(uA + dO1, sH1, szB);
            cpa16(uA + 8192 + dO0, sL0, szA);
            cpa16(uA + 8192 + dO1, sL1, szB);
            CPA_COMMIT();

            const int NCH = I_DIM / 64;  // 8
            for (int ch = 0; ch < NCH; ch++) {
                CPA_WAIT0();
                {
                    char* BH = dsm + 32768 + (ch & 1) * 32768;
                    char* BL = BH + 16384;
                    float cw[4][4];
                    #pragma unroll
                    for (int it = 0; it < 4; it++) {
                        const float* p = wdB + (size_t)(ch * 64 + (pkb + it * 4) * 4) * H_DIM + 64 + pn;
                        cw[it][0] = p[0]; cw[it][1] = p[H_DIM];
                        cw[it][2] = p[2 * H_DIM]; cw[it][3] = p[3 * H_DIM];
                    }
                    #pragma unroll
                    for (int it = 0; it < 4; it++) {
                        uint32_t h01, l01, h23, l23;
                        bsplit2(bw[it][0], bw[it][1], h01, l01);
                        bsplit2(bw[it][2], bw[it][3], h23, l23);
                        uint32_t o = SWZB((uint32_t)(pn * 128 + (pkb + it * 4) * 8));
                        *(uint2*)(BH + o) = make_uint2(h01, h23);
                        *(uint2*)(BL + o) = make_uint2(l01, l23);
                    }
                    #pragma unroll
                    for (int it = 0; it < 4; it++) {
                        uint32_t h01, l01, h23, l23;
                        bsplit2(cw[it][0], cw[it][1], h01, l01);
                        bsplit2(cw[it][2], cw[it][3], h23, l23);
                        uint32_t o = SWZB((uint32_t)((64 + pn) * 128 + (pkb + it * 4) * 8));
                        *(uint2*)(BH + o) = make_uint2(h01, h23);
                        *(uint2*)(BL + o) = make_uint2(l01, l23);
                    }
                }
                __syncthreads();

                if (ch + 1 < NCH) {
                    uint32_t ab = uA + (uint32_t)(((ch + 1) & 1) * 16384);
                    uint32_t boff = (uint32_t)((ch + 1) * 128);
                    cpa16(ab + dO0, sH0 + boff, szA);
                    cpa16(ab + dO1, sH1 + boff, szB);
                    cpa16(ab + 8192 + dO0, sL0 + boff, szA);
                    cpa16(ab + 8192 + dO1, sL1 + boff, szB);
                    CPA_COMMIT();
                    int k0n = (ch + 1) * 64;
                    #pragma unroll
                    for (int it = 0; it < 4; it++) {
                        const float* p = wdB + (size_t)(k0n + (pkb + it * 4) * 4) * H_DIM + pn;
                        bw[it][0] = p[0]; bw[it][1] = p[H_DIM];
                        bw[it][2] = p[2 * H_DIM]; bw[it][3] = p[3 * H_DIM];
                    }
                }

                uint32_t uAhi = uA + (uint32_t)((ch & 1) * 16384);
                uint32_t uAlo = uAhi + 8192;
                uint32_t uBh = uB + (uint32_t)((ch & 1) * 32768);
                uint32_t uBl = uBh + 16384;
                #pragma unroll
                for (int ks = 0; ks < 4; ks++) {
                    uint32_t ah[2][4], al[2][4];
                    #pragma unroll
                    for (int mf = 0; mf < 2; mf++) {
                        uint32_t o = SWZB((uint32_t)((aRow + mf * 16) * 128) + (uint32_t)(ks * 32) + aKb);
                        ldm4(ah[mf], uAhi + o);
                        ldm4(al[mf], uAlo + o);
                    }
                    uint32_t ob1 = SWZB((uint32_t)(bRow * 128) + (uint32_t)(ks * 32) + bKb);
                    uint32_t ob2 = SWZB((uint32_t)((bRow + 16) * 128) + (uint32_t)(ks * 32) + bKb);
                    uint32_t bh[8], bl[8];
                    ldm4(bh, uBh + ob1);
                    ldm4(bh + 4, uBh + ob2);
                    ldm4(bl, uBl + ob1);
                    ldm4(bl + 4, uBl + ob2);
                    #pragma unroll
                    for (int mf = 0; mf < 2; mf++) {
                        #pragma unroll
                        for (int nf = 0; nf < 4; nf++) {
                            mma16816(acc[mf][nf], ah[mf], bh[nf * 2], bh[nf * 2 + 1]);
                            mma16816(acc[mf][nf], ah[mf], bl[nf * 2], bl[nf * 2 + 1]);
                            mma16816(acc[mf][nf], al[mf], bh[nf * 2], bh[nf * 2 + 1]);
                        }
                    }
                }
            }

            #pragma unroll
            for (int mf = 0; mf < 2; mf++) {
                #pragma unroll
                for (int nf = 0; nf < 4; nf++) {
                    int col = nt * 128 + wn * 32 + nf * 8 + lc;
                    #pragma unroll
                    for (int half = 0; half < 2; half++) {
                        int row = wm * 32 + mf * 16 + lr + half * 8;
                        if (m0 + row < ne) {
                            int rid = s_rids[row];
                            float wt = s_wts[row];
                            float2 o;
                            o.x = wt * acc[mf][nf][half * 2 + 0];
                            o.y = wt * acc[mf][nf][half * 2 + 1];
                            *(float2*)(g_ybuf + (size_t)rid * H_DIM + col) = o;
                        }
                    }
                }
            }
        }
    }
}

// ---------------- kernel: deterministic combine ----------------
__global__ __launch_bounds__(256) void combine_kernel(float* __restrict__ out)
{
    int idx = blockIdx.x * 256 + threadIdx.x;
    int t = idx >> 10;
    int h = idx & 1023;
    float s = 0.f;
    #pragma unroll
    for (int k = 0; k < TOPK; k++)
        s += g_ybuf[((size_t)t * TOPK + k) * H_DIM + h];
    out[idx] = s;
}

// ---------------- launch ----------------
#define GEMM_SMEM (32768 + 65536)   // 96KB
#define N_PERSIST 296               // 2 CTAs/SM x 148 SMs

extern "C" void kernel_launch(void* const* d_in, const int* in_sizes, int n_in,
                              void* d_out, int out_size)
{
    const float* x      = (const float*)d_in[0];
    const float* gate_w = (const float*)d_in[1];
    const float* bias   = (const float*)d_in[2];
    const float* Wg     = (const float*)d_in[3];
    const float* Wu     = (const float*)d_in[4];
    const float* Wd     = (const float*)d_in[5];
    float* out = (float*)d_out;

    cudaFuncSetAttribute(moe_gemm_kernel, cudaFuncAttributeMaxDynamicSharedMemorySize, GEMM_SMEM);

    routing_kernel<<<T_TOK, 128>>>(x, gate_w, bias);
    build_lists_kernel<<<1, 1024>>>();
    moe_gemm_kernel<<<N_PERSIST, 256, GEMM_SMEM>>>(Wg, Wu, Wd);
    combine_kernel<<<(T_TOK * H_DIM) / 256, 256>>>(out);
}

// round 10
// speedup vs baseline: 4.7953x; 1.0124x over previous
#include <cuda_runtime.h>
#include <cuda_bf16.h>
#include <math.h>
#include <stdint.h>

#define T_TOK 256
#define H_DIM 1024
#define I_DIM 512
#define E_EXP 32
#define TOPK  8
#define NGRP  8
#define GSZ   4
#define TKG   4

#define SWZB(o) ((o) ^ (((o) >> 3) & 0x70))

// ---------------- helpers ----------------
__device__ __forceinline__ uint32_t smem_u32(const void* p) {
    uint32_t a;
    asm("{ .reg .u64 t; cvta.to.shared.u64 t, %1; cvt.u32.u64 %0, t; }" : "=r"(a) : "l"(p));
    return a;
}

// split 2 fp32 -> packed bf16x2 hi + bf16x2 lo (lo = exact residual)
__device__ __forceinline__ void bsplit2(float e0, float e1, uint32_t &h, uint32_t &l) {
    asm("cvt.rn.bf16x2.f32 %0, %1, %2;" : "=r"(h) : "f"(e1), "f"(e0));
    float f0 = __uint_as_float(h << 16);
    float f1 = __uint_as_float(h & 0xFFFF0000u);
    float r0 = e0 - f0, r1 = e1 - f1;
    asm("cvt.rn.bf16x2.f32 %0, %1, %2;" : "=r"(l) : "f"(r1), "f"(r0));
}

__device__ __forceinline__ void ldm4(uint32_t r[4], uint32_t addr) {
    asm volatile("ldmatrix.sync.aligned.m8n8.x4.shared.b16 {%0,%1,%2,%3}, [%4];"
        : "=r"(r[0]), "=r"(r[1]), "=r"(r[2]), "=r"(r[3]) : "r"(addr));
}

__device__ __forceinline__ void mma16816(float d[4], const uint32_t a[4],
                                         uint32_t b0, uint32_t b1) {
    asm volatile("mma.sync.aligned.m16n8k16.row.col.f32.bf16.bf16.f32 "
        "{%0,%1,%2,%3}, {%4,%5,%6,%7}, {%8,%9}, {%0,%1,%2,%3};"
        : "+f"(d[0]), "+f"(d[1]), "+f"(d[2]), "+f"(d[3])
        : "r"(a[0]), "r"(a[1]), "r"(a[2]), "r"(a[3]), "r"(b0), "r"(b1));
}

__device__ __forceinline__ void cpa16(uint32_t dst, const void* src, uint32_t sz) {
    asm volatile("cp.async.cg.shared.global [%0], [%1], 16, %2;"
        :: "r"(dst), "l"(src), "r"(sz) : "memory");
}
#define CPA_COMMIT() asm volatile("cp.async.commit_group;" ::: "memory")
#define CPA_WAIT0()  asm volatile("cp.async.wait_group 0;" ::: "memory")

// ---------------- device scratch ----------------
__device__ int   g_topk_idx[T_TOK * TOPK];
__device__ float g_topk_w[T_TOK * TOPK];
__device__ int   g_cnt[E_EXP];
__device__ int   g_tok[E_EXP * T_TOK];
__device__ int   g_slot[E_EXP * T_TOK];
__device__ float g_wt[E_EXP * T_TOK];
__device__ uint16_t g_xhi[T_TOK * H_DIM];
__device__ uint16_t g_xlo[T_TOK * H_DIM];
__device__ uint16_t g_ahi[T_TOK * TOPK * I_DIM];
__device__ uint16_t g_alo[T_TOK * TOPK * I_DIM];
__device__ float g_ybuf[T_TOK * TOPK * H_DIM];

// work queue
__device__ int g_pairs[E_EXP * 4];   // (e<<2)|mt
__device__ int g_npair;
__device__ int g_ctr;
__device__ int g_rdy[E_EXP * 4];     // per-pair gateup completion count (target 8)

// ---------------- kernel 1: routing (coalesced GEMV + fused x split) ----------------
__global__ __launch_bounds__(128) void routing_kernel(
    const float* __restrict__ x, const float* __restrict__ gate_w,
    const float* __restrict__ bias)
{
    int t = blockIdx.x;
    __shared__ float xs[H_DIM];
    __shared__ float part[4][E_EXP];
    __shared__ float sc[E_EXP];
    __shared__ float sfc[E_EXP];
    int tid = threadIdx.x;
    for (int i = tid; i < H_DIM / 4; i += 128) {
        float4 v = *(const float4*)(x + (size_t)t * H_DIM + i * 4);
        *(float4*)&xs[i * 4] = v;
        uint32_t h0, l0, h1, l1;
        bsplit2(v.x, v.y, h0, l0);
        bsplit2(v.z, v.w, h1, l1);
        ((uint2*)(g_xhi + (size_t)t * H_DIM))[i] = make_uint2(h0, h1);
        ((uint2*)(g_xlo + (size_t)t * H_DIM))[i] = make_uint2(l0, l1);
    }
    __syncthreads();
    int warp = tid >> 5, lane = tid & 31;
    {
        float s = 0.f;
        const float* gw = gate_w + lane;
        int h0 = warp * (H_DIM / 4);
        #pragma unroll 4
        for (int h = h0; h < h0 + H_DIM / 4; h++)
            s += xs[h] * gw[(size_t)h * E_EXP];
        part[warp][lane] = s;
    }
    __syncthreads();
    if (tid < E_EXP) {
        float s = part[0][tid] + part[1][tid] + part[2][tid] + part[3][tid];
        float sig = 1.f / (1.f + expf(-s));
        sc[tid] = sig;
        sfc[tid] = sig + bias[tid];
    }
    __syncthreads();
    if (tid == 0) {
        float gs[NGRP];
        #pragma unroll
        for (int g = 0; g < NGRP; g++) {
            float m1 = -1e30f, m2 = -1e30f;
            #pragma unroll
            for (int j = 0; j < GSZ; j++) {
                float v = sfc[g * GSZ + j];
                if (v > m1) { m2 = m1; m1 = v; }
                else if (v > m2) { m2 = v; }
            }
            gs[g] = m1 + m2;
        }
        bool gsel[NGRP];
        #pragma unroll
        for (int g = 0; g < NGRP; g++) gsel[g] = false;
        for (int r = 0; r < TKG; r++) {
            int b = -1;
            for (int g = 0; g < NGRP; g++)
                if (!gsel[g] && (b < 0 || gs[g] > gs[b])) b = g;
            gsel[b] = true;
        }
        float masked[E_EXP];
        bool used[E_EXP];
        #pragma unroll
        for (int e = 0; e < E_EXP; e++) {
            masked[e] = gsel[e >> 2] ? sfc[e] : 0.0f;
            used[e] = false;
        }
        int idx[TOPK];
        float wsum = 0.f;
        for (int r = 0; r < TOPK; r++) {
            int b = -1;
            for (int e = 0; e < E_EXP; e++)
                if (!used[e] && (b < 0 || masked[e] > masked[b])) b = e;
            used[b] = true;
            idx[r] = b;
            wsum += sc[b];
        }
        float scale = 2.5f / (wsum + 1e-20f);
        for (int r = 0; r < TOPK; r++) {
            g_topk_idx[t * TOPK + r] = idx[r];
            g_topk_w[t * TOPK + r]   = sc[idx[r]] * scale;
        }
    }
}

// ---------------- kernel 2: compaction + work-queue setup ----------------
__global__ __launch_bounds__(1024) void build_lists_kernel()
{
    int e = threadIdx.x >> 5;
    int lane = threadIdx.x & 31;
    int cnt = 0;
    for (int t0 = 0; t0 < T_TOK; t0 += 32) {
        int t = t0 + lane;
        int found = -1;
        #pragma unroll
        for (int k = 0; k < TOPK; k++)
            if (g_topk_idx[t * TOPK + k] == e) found = k;
        unsigned m = __ballot_sync(0xffffffffu, found >= 0);
        if (found >= 0) {
            int pos = cnt + __popc(m & ((1u << lane) - 1));
            g_tok [e * T_TOK + pos] = t;
            g_slot[e * T_TOK + pos] = found;
            g_wt  [e * T_TOK + pos] = g_topk_w[t * TOPK + found];
        }
        cnt += __popc(m);
    }
    if (lane == 0) g_cnt[e] = cnt;
    if (threadIdx.x < E_EXP * 4) g_rdy[threadIdx.x] = 0;
    __syncthreads();
    if (threadIdx.x == 0) {
        int n = 0;
        for (int ee = 0; ee < E_EXP; ee++) {
            int c = g_cnt[ee];
            for (int mt = 0; mt * 64 < c; mt++) g_pairs[n++] = (ee << 2) | mt;
        }
        g_npair = n;
        g_ctr = 0;
    }
}

// ---------------- fused persistent GEMM kernel ----------------
// smem (96KB): A [0,32K): {A0h,A0l,A1h,A1l}@8K; B bf16 single [32K,64K): {BH 16K, BL 16K};
// W fp32 stage double [64K,96K): {S0 16K, S1 16K}
// Queue: [0, npair*8) gateup tiles (nt in I/64); [npair*8, npair*16) down tiles (nt in H/128).

__global__ __launch_bounds__(256, 2) void moe_gemm_kernel(
    const float* __restrict__ Wg,
    const float* __restrict__ Wu,
    const float* __restrict__ Wd)
{
    extern __shared__ __align__(128) char dsm[];
    __shared__ int   s_widx;
    __shared__ int   s_toks[64];
    __shared__ int   s_rids[64];
    __shared__ float s_wts[64];

    int tid = threadIdx.x;
    int lane = tid & 31;
    int w = tid >> 5;
    int wm = w & 1;
    int wn = w >> 1;   // 0..3

    uint32_t uA = smem_u32(dsm);
    uint32_t uBh = uA + 32768;
    uint32_t uBl = uA + 49152;
    uint32_t uStage = uA + 65536;

    int arow0 = tid >> 3, aseg = tid & 7;
    int arow1 = arow0 + 32;
    uint32_t dO0 = SWZB((uint32_t)(arow0 * 128 + aseg * 16));
    uint32_t dO1 = SWZB((uint32_t)(arow1 * 128 + aseg * 16));

    // weight staging addressing
    int srow = tid >> 2;            // 0..63 (k-row within chunk)
    int sq4  = (tid & 3) * 16;      // float offset of 64B group within 64-float row
    uint32_t stDstBase = (uint32_t)(srow * 256 + (tid & 3) * 64);

    int aRow = wm * 32 + (lane & 15);
    uint32_t aKb = (uint32_t)((lane >> 4) * 16);
    int bRow = wn * 32 + (lane & 7) + ((lane >> 4) << 3);
    uint32_t bKb = (uint32_t)(((lane >> 3) & 1) * 16);

    int pkb = tid >> 6, pn = tid & 63;
    int lr = lane >> 2, lc = (lane & 3) * 2;

    for (;;) {
        __syncthreads();
        if (tid == 0) s_widx = atomicAdd(&g_ctr, 1);
        __syncthreads();
        int widx = s_widx;
        int npair = g_npair;
        if (widx >= npair * 16) return;

        if (widx < npair * 8) {
            // ================= GATEUP TILE =================
            int pidx = widx >> 3;
            int nt = widx & 7;
            int pr = g_pairs[pidx];
            int e = pr >> 2, mt = pr & 3;
            int ne = g_cnt[e];
            int m0 = mt * 64;

            if (tid < 64) {
                int i = m0 + tid;
                if (i < ne) {
                    int tk = g_tok[e * T_TOK + i];
                    s_toks[tid] = tk;
                    s_rids[tid] = tk * TOPK + g_slot[e * T_TOK + i];
                } else { s_toks[tid] = -1; s_rids[tid] = -1; }
            }
            __syncthreads();

            int tokA = s_toks[arow0], tokB = s_toks[arow1];
            const char* sH0 = (const char*)g_xhi + ((size_t)(tokA < 0 ? 0 : tokA) * H_DIM) * 2 + aseg * 16;
            const char* sH1 = (const char*)g_xhi + ((size_t)(tokB < 0 ? 0 : tokB) * H_DIM) * 2 + aseg * 16;
            const char* sL0 = (const char*)g_xlo + ((size_t)(tokA < 0 ? 0 : tokA) * H_DIM) * 2 + aseg * 16;
            const char* sL1 = (const char*)g_xlo + ((size_t)(tokB < 0 ? 0 : tokB) * H_DIM) * 2 + aseg * 16;
            uint32_t szA = (tokA >= 0) ? 16u : 0u;
            uint32_t szB = (tokB >= 0) ? 16u : 0u;

            float acc[2][4][4];
            #pragma unroll
            for (int a = 0; a < 2; a++)
                #pragma unroll
                for (int b = 0; b < 4; b++)
                    #pragma unroll
                    for (int c = 0; c < 4; c++) acc[a][b][c] = 0.f;

            const float* wgB = Wg + (size_t)e * H_DIM * I_DIM + nt * 64;
            const float* wuB = Wu + (size_t)e * H_DIM * I_DIM + nt * 64;
            const float* uSrc = wuB + (size_t)srow * I_DIM + sq4;

            float bw[4][4];
            #pragma unroll
            for (int it = 0; it < 4; it++) {
                const float* p = wgB + (size_t)((pkb + it * 4) * 4) * I_DIM + pn;
                bw[it][0] = p[0]; bw[it][1] = p[I_DIM];
                bw[it][2] = p[2 * I_DIM]; bw[it][3] = p[3 * I_DIM];
            }
            cpa16(uA + dO0, sH0, szA);
            cpa16(uA + dO1, sH1, szB);
            cpa16(uA + 8192 + dO0, sL0, szA);
            cpa16(uA + 8192 + dO1, sL1, szB);
            #pragma unroll
            for (int q = 0; q < 4; q++)
                cpa16(uStage + stDstBase + q * 16, uSrc + q * 4, 16);
            CPA_COMMIT();

            const int NCH = H_DIM / 64;  // 16
            for (int ch = 0; ch < NCH; ch++) {
                CPA_WAIT0();
                __syncthreads();   // make ALL threads' cp.async data visible before stage reads
                // store phase: g-half from bw regs, u-half from fp32 stage (LDS)
                {
                    const float* stgW = (const float*)(dsm + 65536 + (ch & 1) * 16384);
                    #pragma unroll
                    for (int it = 0; it < 4; it++) {
                        uint32_t h01, l01, h23, l23;
                        bsplit2(bw[it][0], bw[it][1], h01, l01);
                        bsplit2(bw[it][2], bw[it][3], h23, l23);
                        uint32_t o = SWZB((uint32_t)(pn * 128 + (pkb + it * 4) * 8));
                        *(uint2*)(dsm + 32768 + o) = make_uint2(h01, h23);
                        *(uint2*)(dsm + 49152 + o) = make_uint2(l01, l23);
                        int kb4 = (pkb + it * 4) * 4;
                        float c0 = stgW[(kb4 + 0) * 64 + pn];
                        float c1 = stgW[(kb4 + 1) * 64 + pn];
                        float c2 = stgW[(kb4 + 2) * 64 + pn];
                        float c3 = stgW[(kb4 + 3) * 64 + pn];
                        bsplit2(c0, c1, h01, l01);
                        bsplit2(c2, c3, h23, l23);
                        uint32_t o2 = SWZB((uint32_t)((64 + pn) * 128 + (pkb + it * 4) * 8));
                        *(uint2*)(dsm + 32768 + o2) = make_uint2(h01, h23);
                        *(uint2*)(dsm + 49152 + o2) = make_uint2(l01, l23);
                    }
                }
                __syncthreads();

                if (ch + 1 < NCH) {
                    uint32_t ab = uA + (uint32_t)(((ch + 1) & 1) * 16384);
                    uint32_t boff = (uint32_t)((ch + 1) * 128);
                    cpa16(ab + dO0, sH0 + boff, szA);
                    cpa16(ab + dO1, sH1 + boff, szB);
                    cpa16(ab + 8192 + dO0, sL0 + boff, szA);
                    cpa16(ab + 8192 + dO1, sL1 + boff, szB);
                    uint32_t sb = uStage + (uint32_t)(((ch + 1) & 1) * 16384);
                    const float* us = uSrc + (size_t)(ch + 1) * 64 * I_DIM;
                    #pragma unroll
                    for (int q = 0; q < 4; q++)
                        cpa16(sb + stDstBase + q * 16, us + q * 4, 16);
                    CPA_COMMIT();
                    int k0n = (ch + 1) * 64;
                    #pragma unroll
                    for (int it = 0; it < 4; it++) {
                        const float* p = wgB + (size_t)(k0n + (pkb + it * 4) * 4) * I_DIM + pn;
                        bw[it][0] = p[0]; bw[it][1] = p[I_DIM];
                        bw[it][2] = p[2 * I_DIM]; bw[it][3] = p[3 * I_DIM];
                    }
                }

                uint32_t uAhi = uA + (uint32_t)((ch & 1) * 16384);
                uint32_t uAlo = uAhi + 8192;
                #pragma unroll
                for (int ks = 0; ks < 4; ks++) {
                    uint32_t ah[2][4], al[2][4];
                    #pragma unroll
                    for (int mf = 0; mf < 2; mf++) {
                        uint32_t o = SWZB((uint32_t)((aRow + mf * 16) * 128) + (uint32_t)(ks * 32) + aKb);
                        ldm4(ah[mf], uAhi + o);
                        ldm4(al[mf], uAlo + o);
                    }
                    uint32_t ob1 = SWZB((uint32_t)(bRow * 128) + (uint32_t)(ks * 32) + bKb);
                    uint32_t ob2 = SWZB((uint32_t)((bRow + 16) * 128) + (uint32_t)(ks * 32) + bKb);
                    uint32_t bh[8], bl[8];
                    ldm4(bh, uBh + ob1);
                    ldm4(bh + 4, uBh + ob2);
                    ldm4(bl, uBl + ob1);
                    ldm4(bl + 4, uBl + ob2);
                    #pragma unroll
                    for (int mf = 0; mf < 2; mf++) {
                        #pragma unroll
                        for (int nf = 0; nf < 4; nf++) {
                            mma16816(acc[mf][nf], ah[mf], bh[nf * 2], bh[nf * 2 + 1]);
                            mma16816(acc[mf][nf], ah[mf], bl[nf * 2], bl[nf * 2 + 1]);
                            mma16816(acc[mf][nf], al[mf], bh[nf * 2], bh[nf * 2 + 1]);
                        }
                    }
                }
                __syncthreads();   // protect single B buffer before next store
            }

            // epilogue: stage to smem, a = silu(g)*u, write bf16 hi/lo
            float* stg = (float*)dsm;
            #pragma unroll
            for (int mf = 0; mf < 2; mf++) {
                #pragma unroll
                for (int nf = 0; nf < 4; nf++) {
                    int col = wn * 32 + nf * 8 + lc;
                    #pragma unroll
                    for (int half = 0; half < 2; half++) {
                        int row = wm * 32 + mf * 16 + lr + half * 8;
                        *(float2*)&stg[row * 128 + col] =
                            make_float2(acc[mf][nf][half * 2], acc[mf][nf][half * 2 + 1]);
                    }
                }
            }
            __syncthreads();
            #pragma unroll
            for (int p = 0; p < 8; p++) {
                int idx2 = tid + p * 256;
                int row = idx2 >> 5;
                int cp = idx2 & 31;
                int rid = s_rids[row];
                if (rid >= 0) {
                    float2 g = *(float2*)&stg[row * 128 + cp * 2];
                    float2 u = *(float2*)&stg[row * 128 + 64 + cp * 2];
                    float a0 = (g.x / (1.f + expf(-g.x))) * u.x;
                    float a1 = (g.y / (1.f + expf(-g.y))) * u.y;
                    uint32_t h, l;
                    bsplit2(a0, a1, h, l);
                    size_t off = (size_t)rid * I_DIM + nt * 64 + cp * 2;
                    *(uint32_t*)(g_ahi + off) = h;
                    *(uint32_t*)(g_alo + off) = l;
                }
            }
            __threadfence();
            __syncthreads();
            if (tid == 0) atomicAdd(&g_rdy[pidx], 1);
        } else {
            // ================= DOWN TILE =================
            int w2 = widx - npair * 8;
            int pidx = w2 >> 3;
            int nt = w2 & 7;
            int pr = g_pairs[pidx];
            int e = pr >> 2, mt = pr & 3;
            int ne = g_cnt[e];
            int m0 = mt * 64;

            if (tid == 0) {
                while (atomicAdd(&g_rdy[pidx], 0) < 8) { }
            }
            __syncthreads();

            if (tid < 64) {
                int i = m0 + tid;
                if (i < ne) {
                    int tk = g_tok[e * T_TOK + i];
                    s_rids[tid] = tk * TOPK + g_slot[e * T_TOK + i];
                    s_wts[tid]  = g_wt[e * T_TOK + i];
                } else { s_rids[tid] = -1; s_wts[tid] = 0.f; }
            }
            __syncthreads();

            int ridA = s_rids[arow0], ridB = s_rids[arow1];
            const char* sH0 = (const char*)g_ahi + ((size_t)(ridA < 0 ? 0 : ridA) * I_DIM) * 2 + aseg * 16;
            const char* sH1 = (const char*)g_ahi + ((size_t)(ridB < 0 ? 0 : ridB) * I_DIM) * 2 + aseg * 16;
            const char* sL0 = (const char*)g_alo + ((size_t)(ridA < 0 ? 0 : ridA) * I_DIM) * 2 + aseg * 16;
            const char* sL1 = (const char*)g_alo + ((size_t)(ridB < 0 ? 0 : ridB) * I_DIM) * 2 + aseg * 16;
            uint32_t szA = (ridA >= 0) ? 16u : 0u;
            uint32_t szB = (ridB >= 0) ? 16u : 0u;

            float acc[2][4][4];
            #pragma unroll
            for (int a = 0; a < 2; a++)
                #pragma unroll
                for (int b = 0; b < 4; b++)
                    #pragma unroll
                    for (int c = 0; c < 4; c++) acc[a][b][c] = 0.f;

            const float* wdB = Wd + (size_t)e * I_DIM * H_DIM + nt * 128;
            const float* uSrc = wdB + 64 + (size_t)srow * H_DIM + sq4;
            float bw[4][4];
            #pragma unroll
            for (int it = 0; it < 4; it++) {
                const float* p = wdB + (size_t)((pkb + it * 4) * 4) * H_DIM + pn;
                bw[it][0] = p[0]; bw[it][1] = p[H_DIM];
                bw[it][2] = p[2 * H_DIM]; bw[it][3] = p[3 * H_DIM];
            }
            cpa16(uA + dO0, sH0, szA);
            cpa16(uA + dO1, sH1, szB);
            cpa16(uA + 8192 + dO0, sL0, szA);
            cpa16(uA + 8192 + dO1, sL1, szB);
            #pragma unroll
            for (int q = 0; q < 4; q++)
                cpa16(uStage + stDstBase + q * 16, uSrc + q * 4, 16);
            CPA_COMMIT();

            const int NCH = I_DIM / 64;  // 8
            for (int ch = 0; ch < NCH; ch++) {
                CPA_WAIT0();
                __syncthreads();   // make ALL threads' cp.async data visible before stage reads
                {
                    const float* stgW = (const float*)(dsm + 65536 + (ch & 1) * 16384);
                    #pragma unroll
                    for (int it = 0; it < 4; it++) {
                        uint32_t h01, l01, h23, l23;
                        bsplit2(bw[it][0], bw[it][1], h01, l01);
                        bsplit2(bw[it][2], bw[it][3], h23, l23);
                        uint32_t o = SWZB((uint32_t)(pn * 128 + (pkb + it * 4) * 8));
                        *(uint2*)(dsm + 32768 + o) = make_uint2(h01, h23);
                        *(uint2*)(dsm + 49152 + o) = make_uint2(l01, l23);
                        int kb4 = (pkb + it * 4) * 4;
                        float c0 = stgW[(kb4 + 0) * 64 + pn];
                        float c1 = stgW[(kb4 + 1) * 64 + pn];
                        float c2 = stgW[(kb4 + 2) * 64 + pn];
                        float c3 = stgW[(kb4 + 3) * 64 + pn];
                        bsplit2(c0, c1, h01, l01);
                        bsplit2(c2, c3, h23, l23);
                        uint32_t o2 = SWZB((uint32_t)((64 + pn) * 128 + (pkb + it * 4) * 8));
                        *(uint2*)(dsm + 32768 + o2) = make_uint2(h01, h23);
                        *(uint2*)(dsm + 49152 + o2) = make_uint2(l01, l23);
                    }
                }
                __syncthreads();

                if (ch + 1 < NCH) {
                    uint32_t ab = uA + (uint32_t)(((ch + 1) & 1) * 16384);
                    uint32_t boff = (uint32_t)((ch + 1) * 128);
                    cpa16(ab + dO0, sH0 + boff, szA);
                    cpa16(ab + dO1, sH1 + boff, szB);
                    cpa16(ab + 8192 + dO0, sL0 + boff, szA);
                    cpa16(ab + 8192 + dO1, sL1 + boff, szB);
                    uint32_t sb = uStage + (uint32_t)(((ch + 1) & 1) * 16384);
                    const float* us = uSrc + (size_t)(ch + 1) * 64 * H_DIM;
                    #pragma unroll
                    for (int q = 0; q < 4; q++)
                        cpa16(sb + stDstBase + q * 16, us + q * 4, 16);
                    CPA_COMMIT();
                    int k0n = (ch + 1) * 64;
                    #pragma unroll
                    for (int it = 0; it < 4; it++) {
                        const float* p = wdB + (size_t)(k0n + (pkb + it * 4) * 4) * H_DIM + pn;
                        bw[it][0] = p[0]; bw[it][1] = p[H_DIM];
                        bw[it][2] = p[2 * H_DIM]; bw[it][3] = p[3 * H_DIM];
                    }
                }

                uint32_t uAhi = uA + (uint32_t)((ch & 1) * 16384);
                uint32_t uAlo = uAhi + 8192;
                #pragma unroll
                for (int ks = 0; ks < 4; ks++) {
                    uint32_t ah[2][4], al[2][4];
                    #pragma unroll
                    for (int mf = 0; mf < 2; mf++) {
                        uint32_t o = SWZB((uint32_t)((aRow + mf * 16) * 128) + (uint32_t)(ks * 32) + aKb);
                        ldm4(ah[mf], uAhi + o);
                        ldm4(al[mf], uAlo + o);
                    }
                    uint32_t ob1 = SWZB((uint32_t)(bRow * 128) + (uint32_t)(ks * 32) + bKb);
                    uint32_t ob2 = SWZB((uint32_t)((bRow + 16) * 128) + (uint32_t)(ks * 32) + bKb);
                    uint32_t bh[8], bl[8];
                    ldm4(bh, uBh + ob1);
                    ldm4(bh + 4, uBh + ob2);
                    ldm4(bl, uBl + ob1);
                    ldm4(bl + 4, uBl + ob2);
                    #pragma unroll
                    for (int mf = 0; mf < 2; mf++) {
                        #pragma unroll
                        for (int nf = 0; nf < 4; nf++) {
                            mma16816(acc[mf][nf], ah[mf], bh[nf * 2], bh[nf * 2 + 1]);
                            mma16816(acc[mf][nf], ah[mf], bl[nf * 2], bl[nf * 2 + 1]);
                            mma16816(acc[mf][nf], al[mf], bh[nf * 2], bh[nf * 2 + 1]);
                        }
                    }
                }
                __syncthreads();
            }

            #pragma unroll
            for (int mf = 0; mf < 2; mf++) {
                #pragma unroll
                for (int nf = 0; nf < 4; nf++) {
                    int col = nt * 128 + wn * 32 + nf * 8 + lc;
                    #pragma unroll
                    for (int half = 0; half < 2; half++) {
                        int row = wm * 32 + mf * 16 + lr + half * 8;
                        if (m0 + row < ne) {
                            int rid = s_rids[row];
                            float wt = s_wts[row];
                            float2 o;
                            o.x = wt * acc[mf][nf][half * 2 + 0];
                            o.y = wt * acc[mf][nf][half * 2 + 1];
                            *(float2*)(g_ybuf + (size_t)rid * H_DIM + col) = o;
                        }
                    }
                }
            }
        }
    }
}

// ---------------- kernel: deterministic combine ----------------
__global__ __launch_bounds__(256) void combine_kernel(float* __restrict__ out)
{
    int idx = blockIdx.x * 256 + threadIdx.x;
    int t = idx >> 10;
    int h = idx & 1023;
    float s = 0.f;
    #pragma unroll
    for (int k = 0; k < TOPK; k++)
        s += g_ybuf[((size_t)t * TOPK + k) * H_DIM + h];
    out[idx] = s;
}

// ---------------- launch ----------------
#define GEMM_SMEM (32768 + 32768 + 32768)   // 96KB
#define N_PERSIST 296

extern "C" void kernel_launch(void* const* d_in, const int* in_sizes, int n_in,
                              void* d_out, int out_size)
{
    const float* x      = (const float*)d_in[0];
    const float* gate_w = (const float*)d_in[1];
    const float* bias   = (const float*)d_in[2];
    const float* Wg     = (const float*)d_in[3];
    const float* Wu     = (const float*)d_in[4];
    const float* Wd     = (const float*)d_in[5];
    float* out = (float*)d_out;

    cudaFuncSetAttribute(moe_gemm_kernel, cudaFuncAttributeMaxDynamicSharedMemorySize, GEMM_SMEM);

    routing_kernel<<<T_TOK, 128>>>(x, gate_w, bias);
    build_lists_kernel<<<1, 1024>>>();
    moe_gemm_kernel<<<N_PERSIST, 256, GEMM_SMEM>>>(Wg, Wu, Wd);
    combine_kernel<<<(T_TOK * H_DIM) / 256, 256>>>(out);
}